// round 14
// baseline (speedup 1.0000x reference)
#include <cuda_runtime.h>
#include <cuda_fp16.h>
#include <stdint.h>
#include <math.h>

/* GEMM-trio pipeline constants */
#define GBK 64             /* k per slab */
#define GASTR 72           /* padded smem stride (144 B rows, 16B aligned) */
#define GNITER 8           /* K=512 / GBK */
#define GSTAGES 3

/* final kernel constants */
#define FBK 32
#define FASTR 40
#define KSPLIT 64
#define KCHUNK 4096
#define BN_LD 136

/* Scratch: __device__ globals (allocation-free rule) */
__device__ uint16_t xd16[32 * 512 * 512];   /* x direct fp16 [b*512+n][h] */
__device__ uint16_t xt16[32 * 512 * 512];   /* x^T fp16 [b][h][m] */
__device__ uint16_t wt16[2 * 512 * 512];    /* Wq^T, Wk^T fp16 [z][n][k] */
__device__ uint16_t q16[32 * 512 * 512];    /* q fp16 */
__device__ uint16_t k16[32 * 512 * 512];    /* k fp16 */
__device__ uint16_t at16[32 * 512 * 512];   /* exp(sigmoid(scores)) fp16 */
__device__ uint16_t ax16[32 * 512 * 512];   /* softmax @ x, fp16 */
__device__ float g_part[KSPLIT * 32 * 512];

/* ------------------------------------------------------------------ */
/* Helpers                                                             */
/* ------------------------------------------------------------------ */
__device__ __forceinline__ uint32_t sptr(const void* p) {
    return (uint32_t)__cvta_generic_to_shared(p);
}

__device__ __forceinline__ void ldsm_x4(uint32_t& r0, uint32_t& r1,
                                        uint32_t& r2, uint32_t& r3,
                                        uint32_t addr) {
    asm volatile("ldmatrix.sync.aligned.m8n8.x4.shared.b16 {%0,%1,%2,%3}, [%4];"
                 : "=r"(r0), "=r"(r1), "=r"(r2), "=r"(r3)
                 : "r"(addr));
}

__device__ __forceinline__ void ldsm_x4_trans(uint32_t& r0, uint32_t& r1,
                                              uint32_t& r2, uint32_t& r3,
                                              uint32_t addr) {
    asm volatile("ldmatrix.sync.aligned.m8n8.x4.trans.shared.b16 {%0,%1,%2,%3}, [%4];"
                 : "=r"(r0), "=r"(r1), "=r"(r2), "=r"(r3)
                 : "r"(addr));
}

__device__ __forceinline__ void mma_f16(float* c, const uint32_t* a,
                                        const uint32_t* b) {
    asm volatile(
        "mma.sync.aligned.m16n8k16.row.col.f32.f16.f16.f32 "
        "{%0,%1,%2,%3}, {%4,%5,%6,%7}, {%8,%9}, {%0,%1,%2,%3};"
        : "+f"(c[0]), "+f"(c[1]), "+f"(c[2]), "+f"(c[3])
        : "r"(a[0]), "r"(a[1]), "r"(a[2]), "r"(a[3]),
          "r"(b[0]), "r"(b[1]));
}

__device__ __forceinline__ void cpa16(uint32_t dst, const void* src) {
    asm volatile("cp.async.cg.shared.global [%0], [%1], 16;"
                 :: "r"(dst), "l"(src) : "memory");
}
__device__ __forceinline__ void cpa_commit() {
    asm volatile("cp.async.commit_group;" ::: "memory");
}
template <int N>
__device__ __forceinline__ void cpa_wait() {
    asm volatile("cp.async.wait_group %0;" :: "n"(N) : "memory");
}

__device__ __forceinline__ uint16_t h1(float v) {
    __half h = __float2half_rn(v);
    return *reinterpret_cast<uint16_t*>(&h);
}

__device__ __forceinline__ void pack8_plain(const float* v, uint4& u) {
    uint16_t h[8];
#pragma unroll
    for (int j = 0; j < 8; j++) {
        h[j] = h1(v[j]);
    }
    u.x = (uint32_t)h[0] | ((uint32_t)h[1] << 16);
    u.y = (uint32_t)h[2] | ((uint32_t)h[3] << 16);
    u.z = (uint32_t)h[4] | ((uint32_t)h[5] << 16);
    u.w = (uint32_t)h[6] | ((uint32_t)h[7] << 16);
}

__device__ __forceinline__ float h2sum(uint32_t r) {
    float2 f = __half22float2(*reinterpret_cast<__half2*>(&r));
    return f.x + f.y;
}

/* ------------------------------------------------------------------ */
/* Compute: one GBK=64 slab, 128x128 CTA tile, 16 warps (wm 4 x wn 4), */
/* warp tile 32x32, acc[2][4][4] = 32 regs. Optional A row-sums.       */
/* ------------------------------------------------------------------ */
template <bool SUMS>
__device__ __forceinline__ void compute128_h(uint32_t sA, uint32_t sB,
                                             int wm, int wn, int lane,
                                             float acc[2][4][4],
                                             float* s0, float* s1) {
    const int lr = (lane & 7) + ((lane >> 3) & 1) * 8;
    const int lc = (lane >> 4) * 8;

#pragma unroll
    for (int h = 0; h < 4; h++) {
        uint32_t b[4][2];
#pragma unroll
        for (int p = 0; p < 2; p++) {
            uint32_t off = (uint32_t)(((wn * 32 + p * 16 + lr) * GASTR + h * 16 + lc) * 2);
            uint32_t r0, r1, r2, r3;
            ldsm_x4(r0, r1, r2, r3, sB + off);
            b[2 * p][0] = r0;
            b[2 * p][1] = r2;
            b[2 * p + 1][0] = r1;
            b[2 * p + 1][1] = r3;
        }
        uint32_t a[2][4];
#pragma unroll
        for (int mt = 0; mt < 2; mt++) {
            uint32_t off = (uint32_t)(((wm * 32 + mt * 16 + lr) * GASTR + h * 16 + lc) * 2);
            ldsm_x4(a[mt][0], a[mt][1], a[mt][2], a[mt][3], sA + off);
        }
        if (SUMS) {
#pragma unroll
            for (int mt = 0; mt < 2; mt++) {
                s0[mt] += h2sum(a[mt][0]) + h2sum(a[mt][2]);
                s1[mt] += h2sum(a[mt][1]) + h2sum(a[mt][3]);
            }
        }
#pragma unroll
        for (int mt = 0; mt < 2; mt++) {
#pragma unroll
            for (int nt = 0; nt < 4; nt++) {
                mma_f16(acc[mt][nt], a[mt], b[nt]);
            }
        }
    }
}

/* ------------------------------------------------------------------ */
/* Prep 1: x -> direct fp16 (xd16) AND transposed fp16 (xt16).         */
/* ------------------------------------------------------------------ */
__global__ __launch_bounds__(256) void prep_x(const float* __restrict__ x) {
    __shared__ float ts[64][65];
    const int tid = threadIdx.x;
    const int m0 = blockIdx.y * 64;
    const int h0 = blockIdx.x * 64;
    const size_t off = (size_t)blockIdx.z * 262144;
    const float* src = x + off + (size_t)m0 * 512 + h0;

#pragma unroll
    for (int i = 0; i < 4; i++) {
        int lin = i * 256 + tid;
        int r = lin >> 4;
        int c4 = (lin & 15) * 4;
        float4 v = *(const float4*)(src + (size_t)r * 512 + c4);
        ts[r][c4 + 0] = v.x;
        ts[r][c4 + 1] = v.y;
        ts[r][c4 + 2] = v.z;
        ts[r][c4 + 3] = v.w;
    }
    __syncthreads();

#pragma unroll
    for (int i = 0; i < 2; i++) {
        int lin = i * 256 + tid;
        int r = lin >> 3;
        int c8 = (lin & 7) * 8;
        float v[8];
#pragma unroll
        for (int j = 0; j < 8; j++) {
            v[j] = ts[r][c8 + j];
        }
        uint4 u;
        pack8_plain(v, u);
        *(uint4*)(xd16 + off + (size_t)(m0 + r) * 512 + h0 + c8) = u;
    }
#pragma unroll
    for (int i = 0; i < 2; i++) {
        int lin = i * 256 + tid;
        int hr = lin >> 3;
        int m8 = (lin & 7) * 8;
        float v[8];
#pragma unroll
        for (int j = 0; j < 8; j++) {
            v[j] = ts[m8 + j][hr];
        }
        uint4 u;
        pack8_plain(v, u);
        *(uint4*)(xt16 + off + (size_t)(h0 + hr) * 512 + m0 + m8) = u;
    }
}

/* ------------------------------------------------------------------ */
/* Prep 2: Wq/Wk -> transposed plain fp16 (wt16). grid (8,8,2).        */
/* ------------------------------------------------------------------ */
__global__ __launch_bounds__(256) void prep_wt(const float* __restrict__ Wq,
                                               const float* __restrict__ Wk) {
    __shared__ float ts[64][65];
    const int tid = threadIdx.x;
    const int k0 = blockIdx.y * 64;
    const int n0 = blockIdx.x * 64;
    const float* src = (blockIdx.z ? Wk : Wq) + (size_t)k0 * 512 + n0;
    const size_t dstoff = (size_t)blockIdx.z * 262144;

#pragma unroll
    for (int i = 0; i < 4; i++) {
        int lin = i * 256 + tid;
        int r = lin >> 4;
        int c4 = (lin & 15) * 4;
        float4 v = *(const float4*)(src + (size_t)r * 512 + c4);
        ts[r][c4 + 0] = v.x;
        ts[r][c4 + 1] = v.y;
        ts[r][c4 + 2] = v.z;
        ts[r][c4 + 3] = v.w;
    }
    __syncthreads();

#pragma unroll
    for (int i = 0; i < 2; i++) {
        int lin = i * 256 + tid;
        int nr = lin >> 3;
        int k8 = (lin & 7) * 8;
        float v[8];
#pragma unroll
        for (int j = 0; j < 8; j++) {
            v[j] = ts[k8 + j][nr];
        }
        uint4 u;
        pack8_plain(v, u);
        *(uint4*)(wt16 + dstoff + (size_t)(n0 + nr) * 512 + k0 + k8) = u;
    }
}

/* ------------------------------------------------------------------ */
/* Generic plain-fp16 GEMM body: 3-stage cp.async pipeline, GBK=64,    */
/* 512 threads. Pointer-increment addressing.                          */
/* ------------------------------------------------------------------ */
#define PTILE (128 * GASTR)                  /* elems per array */
#define STAGE_BYTES (2 * PTILE * 2)          /* 36864 */
#define GSMEM_BYTES (GSTAGES * STAGE_BYTES)  /* 110592 */

template <bool SUMS>
__device__ __forceinline__ void gemm128_body(
    const uint16_t* __restrict__ A, const uint16_t* __restrict__ B,
    uint32_t s0addr, int tid, int wm, int wn, int lane, float acc[2][4][4],
    float* s0, float* s1) {
    const int trow = tid >> 3;
    const int tcol = (tid & 7) * 8;
    const uint16_t* pa = A + (size_t)trow * 512 + tcol;
    const uint16_t* pb = B + (size_t)trow * 512 + tcol;
    const uint32_t soff = (uint32_t)(trow * GASTR + tcol) * 2;

#pragma unroll
    for (int s = 0; s < GSTAGES - 1; s++) {
        uint32_t sb = s0addr + s * STAGE_BYTES + soff;
#pragma unroll
        for (int i = 0; i < 2; i++) {
            cpa16(sb + i * (64 * GASTR * 2), pa + i * (64 * 512));
            cpa16(sb + PTILE * 2 + i * (64 * GASTR * 2), pb + i * (64 * 512));
        }
        cpa_commit();
        pa += GBK;
        pb += GBK;
    }

    int cur = 0;
    int nxt = 2;
    for (int c = 0; c < GNITER; c++) {
        cpa_wait<1>();
        __syncthreads();
        if (c + GSTAGES - 1 < GNITER) {
            uint32_t sb = s0addr + nxt * STAGE_BYTES + soff;
#pragma unroll
            for (int i = 0; i < 2; i++) {
                cpa16(sb + i * (64 * GASTR * 2), pa + i * (64 * 512));
                cpa16(sb + PTILE * 2 + i * (64 * GASTR * 2), pb + i * (64 * 512));
            }
            pa += GBK;
            pb += GBK;
        }
        cpa_commit();
        uint32_t sb = s0addr + cur * STAGE_BYTES;
        compute128_h<SUMS>(sb, sb + PTILE * 2, wm, wn, lane, acc, s0, s1);
        cur = (cur == 2) ? 0 : cur + 1;
        nxt = (nxt == 2) ? 0 : nxt + 1;
    }
}

/* ------------------------------------------------------------------ */
/* Kernel: q/k projections. grid (4, 128, 2), 512 thr, 2 CTAs/SM.      */
/* ------------------------------------------------------------------ */
__global__ __launch_bounds__(512, 2) void proj_kernel(
    const float* __restrict__ bq, const float* __restrict__ bk) {
    extern __shared__ uint16_t dynsm[];

    const int tid = threadIdx.x;
    const int lane = tid & 31;
    const int wid = tid >> 5;
    const int wm = wid & 3;
    const int wn = wid >> 2;
    const int z = blockIdx.z;
    const int row0 = blockIdx.y * 128;
    const int col0 = blockIdx.x * 128;

    const uint16_t* A = xd16 + (size_t)row0 * 512;
    const uint16_t* B = wt16 + (size_t)z * 262144 + (size_t)col0 * 512;

    float acc[2][4][4] = {};
    gemm128_body<false>(A, B, sptr(dynsm), tid, wm, wn, lane, acc, nullptr, nullptr);

    const float* bias = z ? bk : bq;
    uint16_t* O = z ? k16 : q16;
    const int g = lane >> 2;
    const int tg2 = (lane & 3) * 2;
#pragma unroll
    for (int mt = 0; mt < 2; mt++) {
        int r = row0 + wm * 32 + mt * 16 + g;
#pragma unroll
        for (int nt = 0; nt < 4; nt++) {
            int c = col0 + wn * 32 + nt * 8 + tg2;
            float2 bv = *(const float2*)(bias + c);
            __half2 p0 = __floats2half2_rn(acc[mt][nt][0] + bv.x, acc[mt][nt][1] + bv.y);
            __half2 p1 = __floats2half2_rn(acc[mt][nt][2] + bv.x, acc[mt][nt][3] + bv.y);
            *(uint32_t*)(O + (size_t)r * 512 + c) = *reinterpret_cast<uint32_t*>(&p0);
            *(uint32_t*)(O + (size_t)(r + 8) * 512 + c) = *reinterpret_cast<uint32_t*>(&p1);
        }
    }
}

/* ------------------------------------------------------------------ */
/* Kernel: scores -> at16 = exp(sigmoid(q k^T / sqrt(512))) fp16.      */
/* ------------------------------------------------------------------ */
__device__ __forceinline__ float esig(float x, float scale) {
    return __expf(__fdividef(1.f, 1.f + __expf(-x * scale)));
}

__global__ __launch_bounds__(512, 2) void scores_kernel() {
    extern __shared__ uint16_t dynsm[];

    const int tid = threadIdx.x;
    const int lane = tid & 31;
    const int wid = tid >> 5;
    const int wm = wid & 3;
    const int wn = wid >> 2;
    const int b = blockIdx.z;
    const int row0 = blockIdx.y * 128;
    const int col0 = blockIdx.x * 128;

    const uint16_t* A = q16 + ((size_t)b * 512 + row0) * 512;
    const uint16_t* B = k16 + ((size_t)b * 512 + col0) * 512;

    float acc[2][4][4] = {};
    gemm128_body<false>(A, B, sptr(dynsm), tid, wm, wn, lane, acc, nullptr, nullptr);

    const float scale = 0.04419417382415922f; /* 1/sqrt(512) */
    uint16_t* E = at16 + (size_t)b * 262144;
    const int g = lane >> 2;
    const int tg2 = (lane & 3) * 2;
#pragma unroll
    for (int mt = 0; mt < 2; mt++) {
        int r = row0 + wm * 32 + mt * 16 + g;
#pragma unroll
        for (int nt = 0; nt < 4; nt++) {
            int c = col0 + wn * 32 + nt * 8 + tg2;
            __half2 p0 = __floats2half2_rn(esig(acc[mt][nt][0], scale),
                                           esig(acc[mt][nt][1], scale));
            __half2 p1 = __floats2half2_rn(esig(acc[mt][nt][2], scale),
                                           esig(acc[mt][nt][3], scale));
            *(uint32_t*)(E + (size_t)r * 512 + c) = *reinterpret_cast<uint32_t*>(&p0);
            *(uint32_t*)(E + (size_t)(r + 8) * 512 + c) = *reinterpret_cast<uint32_t*>(&p1);
        }
    }
}

/* ------------------------------------------------------------------ */
/* Kernel: ax = softmax @ x. A row-sums computed in the mainloop from  */
/* the exp fragments; epilogue scales by 1/sum locally. CTAs with      */
/* blockIdx.x==0 also write the normalized fp32 attn output.           */
/* grid (4,4,32), 512 thr.                                             */
/* ------------------------------------------------------------------ */
__global__ __launch_bounds__(512, 2) void ax_kernel(float* __restrict__ attn) {
    extern __shared__ uint16_t dynsm[];
    __shared__ float rs[128];

    const int tid = threadIdx.x;
    const int lane = tid & 31;
    const int wid = tid >> 5;
    const int wm = wid & 3;
    const int wn = wid >> 2;
    const int b = blockIdx.z;
    const int row0 = blockIdx.y * 128;
    const int col0 = blockIdx.x * 128;

    const uint16_t* A = at16 + ((size_t)b * 512 + row0) * 512;
    const uint16_t* B = xt16 + ((size_t)b * 512 + col0) * 512;

    float acc[2][4][4] = {};
    float s0[2] = {0.f, 0.f};
    float s1[2] = {0.f, 0.f};
    gemm128_body<true>(A, B, sptr(dynsm), tid, wm, wn, lane, acc, s0, s1);

    /* complete row sums across the 4 lanes of each quad */
#pragma unroll
    for (int mt = 0; mt < 2; mt++) {
        s0[mt] += __shfl_xor_sync(0xffffffffu, s0[mt], 1);
        s0[mt] += __shfl_xor_sync(0xffffffffu, s0[mt], 2);
        s1[mt] += __shfl_xor_sync(0xffffffffu, s1[mt], 1);
        s1[mt] += __shfl_xor_sync(0xffffffffu, s1[mt], 2);
    }

    const size_t rowg = (size_t)b * 512;
    const int g = lane >> 2;
    const int tg2 = (lane & 3) * 2;
#pragma unroll
    for (int mt = 0; mt < 2; mt++) {
        int r = row0 + wm * 32 + mt * 16 + g;
        float i0 = 1.f / s0[mt];
        float i1 = 1.f / s1[mt];
        if (blockIdx.x == 0 && wn == 0 && (lane & 3) == 0) {
            rs[wm * 32 + mt * 16 + g] = i0;
            rs[wm * 32 + mt * 16 + g + 8] = i1;
        }
#pragma unroll
        for (int nt = 0; nt < 4; nt++) {
            int c = col0 + wn * 32 + nt * 8 + tg2;
            __half2 p0 = __floats2half2_rn(acc[mt][nt][0] * i0, acc[mt][nt][1] * i0);
            __half2 p1 = __floats2half2_rn(acc[mt][nt][2] * i1, acc[mt][nt][3] * i1);
            *(uint32_t*)(ax16 + (rowg + r) * 512 + c) = *reinterpret_cast<uint32_t*>(&p0);
            *(uint32_t*)(ax16 + (rowg + r + 8) * 512 + c) = *reinterpret_cast<uint32_t*>(&p1);
        }
    }

    /* col-tile 0 CTAs: write normalized fp32 attention for their rows */
    if (blockIdx.x == 0) {
        __syncthreads();
        const int rl = tid >> 2;           /* 0..127 */
        const int cb = (tid & 3) * 128;    /* col base */
        const float rv = rs[rl];
        const uint16_t* src = at16 + (rowg + row0 + rl) * 512 + cb;
        float* dst = attn + (size_t)b * 262144 + (size_t)(row0 + rl) * 512 + cb;
#pragma unroll 8
        for (int i = 0; i < 32; i++) {
            uint2 u = *(const uint2*)(src + i * 4);
            float2 f0 = __half22float2(*reinterpret_cast<__half2*>(&u.x));
            float2 f1 = __half22float2(*reinterpret_cast<__half2*>(&u.y));
            float4 o;
            o.x = f0.x * rv;
            o.y = f0.y * rv;
            o.z = f1.x * rv;
            o.w = f1.y * rv;
            *(float4*)(dst + i * 4) = o;
        }
    }
}

/* ------------------------------------------------------------------ */
/* Kernel: split-K partials of out = ax.reshape(32,262144) @ Wm.       */
/* (unchanged — measured at the LTS bandwidth cap)                     */
/* ------------------------------------------------------------------ */
#define FAEL (32 * FASTR)              /* A stage elems: [m][k] */
#define FBEL (32 * BN_LD)              /* B stage elems: [k][n] */
#define FSTAGE (FAEL + FBEL)

__global__ __launch_bounds__(256, 2) void final_kernel(const float* __restrict__ Wm) {
    __shared__ alignas(16) uint16_t dsm[2 * FSTAGE];

    const int tid = threadIdx.x;
    const int lane = tid & 31;
    const int wid = tid >> 5;
    const int col0 = blockIdx.x * 128;
    const size_t kbase = (size_t)blockIdx.y * KCHUNK;

    float acc[2][2][4] = {};
    uint2 va;
    float4 vb[4];
    const int am = tid >> 3;
    const int ak = (tid & 7) * 4;
    const int bk_r = tid >> 5;
    const int bn4 = (tid & 31) * 4;

    va = *(const uint2*)(ax16 + (size_t)am * 262144 + kbase + ak);
#pragma unroll
    for (int i = 0; i < 4; i++) {
        vb[i] = *(const float4*)(Wm + (kbase + bk_r + i * 8) * 512 + col0 + bn4);
    }

    auto store_stage = [&](uint16_t* stg) {
        *(uint2*)(stg + am * FASTR + ak) = va;
        uint16_t* bs = stg + FAEL;
#pragma unroll
        for (int i = 0; i < 4; i++) {
            __half2 p0 = __floats2half2_rn(vb[i].x, vb[i].y);
            __half2 p1 = __floats2half2_rn(vb[i].z, vb[i].w);
            uint2 u;
            u.x = *reinterpret_cast<uint32_t*>(&p0);
            u.y = *reinterpret_cast<uint32_t*>(&p1);
            *(uint2*)(bs + (bk_r + i * 8) * BN_LD + bn4) = u;
        }
    };

    store_stage(dsm);
    va = *(const uint2*)(ax16 + (size_t)am * 262144 + kbase + FBK + ak);
#pragma unroll
    for (int i = 0; i < 4; i++) {
        vb[i] = *(const float4*)(Wm + (kbase + FBK + bk_r + i * 8) * 512 + col0 + bn4);
    }
    __syncthreads();

    const int lr = (lane & 7) + ((lane >> 3) & 1) * 8;
    const int lc = (lane >> 4) * 8;
    const int trow = (lane >> 4) * 8 + (lane & 7);
    const int tcol = ((lane >> 3) & 1) * 8;

    for (int k0 = 0; k0 < KCHUNK; k0 += FBK) {
        int cur = (k0 >> 5) & 1;
        if (k0 + FBK < KCHUNK) {
            store_stage(dsm + (cur ^ 1) * FSTAGE);
        }
        if (k0 + 2 * FBK < KCHUNK) {
            va = *(const uint2*)(ax16 + (size_t)am * 262144 + kbase + k0 + 2 * FBK + ak);
#pragma unroll
            for (int i = 0; i < 4; i++) {
                vb[i] = *(const float4*)(Wm + (kbase + k0 + 2 * FBK + bk_r + i * 8) * 512 +
                                         col0 + bn4);
            }
        }
        uint32_t base = sptr(dsm) + cur * FSTAGE * 2;
        uint32_t sA = base;
        uint32_t sB = base + FAEL * 2;
#pragma unroll
        for (int ks = 0; ks < FBK; ks += 16) {
            uint32_t bf[2][2];
            uint32_t offb = (uint32_t)(((ks + trow) * BN_LD + wid * 16 + tcol) * 2);
            uint32_t r0, r1, r2, r3;
            ldsm_x4_trans(r0, r1, r2, r3, sB + offb);
            bf[0][0] = r0;
            bf[1][0] = r1;
            bf[0][1] = r2;
            bf[1][1] = r3;
            uint32_t a[2][4];
#pragma unroll
            for (int mt = 0; mt < 2; mt++) {
                uint32_t offa = (uint32_t)(((mt * 16 + lr) * FASTR + ks + lc) * 2);
                ldsm_x4(a[mt][0], a[mt][1], a[mt][2], a[mt][3], sA + offa);
            }
#pragma unroll
            for (int mt = 0; mt < 2; mt++) {
#pragma unroll
                for (int nt = 0; nt < 2; nt++) {
                    mma_f16(acc[mt][nt], a[mt], bf[nt]);
                }
            }
        }
        __syncthreads();
    }

    const int g = lane >> 2;
    const int tg2 = (lane & 3) * 2;
    float* P = g_part + (size_t)blockIdx.y * 16384;
#pragma unroll
    for (int mt = 0; mt < 2; mt++) {
        int r = mt * 16 + g;
#pragma unroll
        for (int nt = 0; nt < 2; nt++) {
            int c = col0 + wid * 16 + nt * 8 + tg2;
            float2 o0;
            float2 o1;
            o0.x = acc[mt][nt][0];
            o0.y = acc[mt][nt][1];
            o1.x = acc[mt][nt][2];
            o1.y = acc[mt][nt][3];
            *(float2*)(P + (size_t)r * 512 + c) = o0;
            *(float2*)(P + (size_t)(r + 8) * 512 + c) = o1;
        }
    }
}

/* ------------------------------------------------------------------ */
/* Kernel: deterministic split-K reduce + bias. grid 64 x 256.         */
/* ------------------------------------------------------------------ */
__global__ __launch_bounds__(256) void reduce_kernel(float* __restrict__ out,
                                                     const float* __restrict__ bm) {
    const int idx = blockIdx.x * 256 + threadIdx.x;
    const int n = idx & 511;
    float sum = bm[n];
#pragma unroll 8
    for (int s = 0; s < KSPLIT; s++) {
        sum += g_part[(size_t)s * 16384 + idx];
    }
    out[idx] = sum;
}

/* ------------------------------------------------------------------ */
extern "C" void kernel_launch(void* const* d_in, const int* in_sizes, int n_in,
                              void* d_out, int out_size) {
    const float* x = (const float*)d_in[0];
    const float* Wq = (const float*)d_in[1];
    const float* bq = (const float*)d_in[2];
    const float* Wk = (const float*)d_in[3];
    const float* bk = (const float*)d_in[4];
    const float* Wm = (const float*)d_in[5];
    const float* bm = (const float*)d_in[6];

    float* out = (float*)d_out;   /* [32, 512] */
    float* attn = out + 32 * 512; /* [32, 512, 512] */

    cudaFuncSetAttribute(proj_kernel, cudaFuncAttributeMaxDynamicSharedMemorySize,
                         GSMEM_BYTES);
    cudaFuncSetAttribute(scores_kernel, cudaFuncAttributeMaxDynamicSharedMemorySize,
                         GSMEM_BYTES);
    cudaFuncSetAttribute(ax_kernel, cudaFuncAttributeMaxDynamicSharedMemorySize,
                         GSMEM_BYTES);

    prep_x<<<dim3(8, 8, 32), 256>>>(x);
    prep_wt<<<dim3(8, 8, 2), 256>>>(Wq, Wk);
    proj_kernel<<<dim3(4, 128, 2), 512, GSMEM_BYTES>>>(bq, bk);
    scores_kernel<<<dim3(4, 4, 32), 512, GSMEM_BYTES>>>();
    ax_kernel<<<dim3(4, 4, 32), 512, GSMEM_BYTES>>>(attn);
    final_kernel<<<dim3(4, KSPLIT), 256>>>(Wm);
    reduce_kernel<<<64, 256>>>(out, bm);
}

// round 15
// speedup vs baseline: 1.0606x; 1.0606x over previous
#include <cuda_runtime.h>
#include <cuda_fp16.h>
#include <stdint.h>
#include <math.h>

/* GEMM-trio pipeline constants */
#define GBK 64             /* k per slab */
#define GASTR 72           /* padded smem stride (144 B rows, 16B aligned) */
#define GNITER 8           /* K=512 / GBK */
#define GSTAGES 3

/* final kernel constants */
#define FBK 32
#define FASTR 40
#define KSPLIT 64
#define KCHUNK 4096
#define BN_LD 136

/* Scratch: __device__ globals (allocation-free rule) */
__device__ uint16_t xd16[32 * 512 * 512];   /* x direct fp16 [b*512+n][h] */
__device__ uint16_t xt16[32 * 512 * 512];   /* x^T fp16 [b][h][m] */
__device__ uint16_t wt16[2 * 512 * 512];    /* Wq^T, Wk^T fp16 [z][n][k] */
__device__ uint16_t q16[32 * 512 * 512];    /* q fp16 */
__device__ uint16_t k16[32 * 512 * 512];    /* k fp16 */
__device__ uint16_t at16[32 * 512 * 512];   /* exp(sigmoid(scores)) fp16 */
__device__ uint16_t ax16[32 * 512 * 512];   /* softmax @ x, fp16 */
__device__ float g_part[KSPLIT * 32 * 512];

/* ------------------------------------------------------------------ */
/* Helpers                                                             */
/* ------------------------------------------------------------------ */
__device__ __forceinline__ uint32_t sptr(const void* p) {
    return (uint32_t)__cvta_generic_to_shared(p);
}

__device__ __forceinline__ void ldsm_x4(uint32_t& r0, uint32_t& r1,
                                        uint32_t& r2, uint32_t& r3,
                                        uint32_t addr) {
    asm volatile("ldmatrix.sync.aligned.m8n8.x4.shared.b16 {%0,%1,%2,%3}, [%4];"
                 : "=r"(r0), "=r"(r1), "=r"(r2), "=r"(r3)
                 : "r"(addr));
}

__device__ __forceinline__ void ldsm_x4_trans(uint32_t& r0, uint32_t& r1,
                                              uint32_t& r2, uint32_t& r3,
                                              uint32_t addr) {
    asm volatile("ldmatrix.sync.aligned.m8n8.x4.trans.shared.b16 {%0,%1,%2,%3}, [%4];"
                 : "=r"(r0), "=r"(r1), "=r"(r2), "=r"(r3)
                 : "r"(addr));
}

__device__ __forceinline__ void mma_f16(float* c, const uint32_t* a,
                                        const uint32_t* b) {
    asm volatile(
        "mma.sync.aligned.m16n8k16.row.col.f32.f16.f16.f32 "
        "{%0,%1,%2,%3}, {%4,%5,%6,%7}, {%8,%9}, {%0,%1,%2,%3};"
        : "+f"(c[0]), "+f"(c[1]), "+f"(c[2]), "+f"(c[3])
        : "r"(a[0]), "r"(a[1]), "r"(a[2]), "r"(a[3]),
          "r"(b[0]), "r"(b[1]));
}

__device__ __forceinline__ void cpa16(uint32_t dst, const void* src) {
    asm volatile("cp.async.cg.shared.global [%0], [%1], 16;"
                 :: "r"(dst), "l"(src) : "memory");
}
__device__ __forceinline__ void cpa_commit() {
    asm volatile("cp.async.commit_group;" ::: "memory");
}
template <int N>
__device__ __forceinline__ void cpa_wait() {
    asm volatile("cp.async.wait_group %0;" :: "n"(N) : "memory");
}

__device__ __forceinline__ uint16_t h1(float v) {
    __half h = __float2half_rn(v);
    return *reinterpret_cast<uint16_t*>(&h);
}

__device__ __forceinline__ void pack8_plain(const float* v, uint4& u) {
    uint16_t h[8];
#pragma unroll
    for (int j = 0; j < 8; j++) {
        h[j] = h1(v[j]);
    }
    u.x = (uint32_t)h[0] | ((uint32_t)h[1] << 16);
    u.y = (uint32_t)h[2] | ((uint32_t)h[3] << 16);
    u.z = (uint32_t)h[4] | ((uint32_t)h[5] << 16);
    u.w = (uint32_t)h[6] | ((uint32_t)h[7] << 16);
}

/* ------------------------------------------------------------------ */
/* Compute: one GBK=64 slab, 128x128 CTA tile, 16 warps (wm 4 x wn 4), */
/* warp tile 32x32. SUMS: wn==0 warps also accumulate A-row sums via   */
/* an extra MMA against an all-ones B fragment (sacc[mt][0]/[2] end up */
/* holding the full row sums for rows g and g+8).                      */
/* ------------------------------------------------------------------ */
template <bool SUMS>
__device__ __forceinline__ void compute128_h(uint32_t sA, uint32_t sB,
                                             int wm, int wn, int lane,
                                             float acc[2][4][4],
                                             float sacc[2][4]) {
    const int lr = (lane & 7) + ((lane >> 3) & 1) * 8;
    const int lc = (lane >> 4) * 8;
    const uint32_t ones[2] = {0x3C003C00u, 0x3C003C00u};

#pragma unroll
    for (int h = 0; h < 4; h++) {
        uint32_t b[4][2];
#pragma unroll
        for (int p = 0; p < 2; p++) {
            uint32_t off = (uint32_t)(((wn * 32 + p * 16 + lr) * GASTR + h * 16 + lc) * 2);
            uint32_t r0, r1, r2, r3;
            ldsm_x4(r0, r1, r2, r3, sB + off);
            b[2 * p][0] = r0;
            b[2 * p][1] = r2;
            b[2 * p + 1][0] = r1;
            b[2 * p + 1][1] = r3;
        }
        uint32_t a[2][4];
#pragma unroll
        for (int mt = 0; mt < 2; mt++) {
            uint32_t off = (uint32_t)(((wm * 32 + mt * 16 + lr) * GASTR + h * 16 + lc) * 2);
            ldsm_x4(a[mt][0], a[mt][1], a[mt][2], a[mt][3], sA + off);
        }
        if (SUMS) {
            if (wn == 0) {
#pragma unroll
                for (int mt = 0; mt < 2; mt++) {
                    mma_f16(sacc[mt], a[mt], ones);
                }
            }
        }
#pragma unroll
        for (int mt = 0; mt < 2; mt++) {
#pragma unroll
            for (int nt = 0; nt < 4; nt++) {
                mma_f16(acc[mt][nt], a[mt], b[nt]);
            }
        }
    }
}

/* ------------------------------------------------------------------ */
/* Prep 1: x -> direct fp16 (xd16) AND transposed fp16 (xt16).         */
/* ------------------------------------------------------------------ */
__global__ __launch_bounds__(256) void prep_x(const float* __restrict__ x) {
    __shared__ float ts[64][65];
    const int tid = threadIdx.x;
    const int m0 = blockIdx.y * 64;
    const int h0 = blockIdx.x * 64;
    const size_t off = (size_t)blockIdx.z * 262144;
    const float* src = x + off + (size_t)m0 * 512 + h0;

#pragma unroll
    for (int i = 0; i < 4; i++) {
        int lin = i * 256 + tid;
        int r = lin >> 4;
        int c4 = (lin & 15) * 4;
        float4 v = *(const float4*)(src + (size_t)r * 512 + c4);
        ts[r][c4 + 0] = v.x;
        ts[r][c4 + 1] = v.y;
        ts[r][c4 + 2] = v.z;
        ts[r][c4 + 3] = v.w;
    }
    __syncthreads();

#pragma unroll
    for (int i = 0; i < 2; i++) {
        int lin = i * 256 + tid;
        int r = lin >> 3;
        int c8 = (lin & 7) * 8;
        float v[8];
#pragma unroll
        for (int j = 0; j < 8; j++) {
            v[j] = ts[r][c8 + j];
        }
        uint4 u;
        pack8_plain(v, u);
        *(uint4*)(xd16 + off + (size_t)(m0 + r) * 512 + h0 + c8) = u;
    }
#pragma unroll
    for (int i = 0; i < 2; i++) {
        int lin = i * 256 + tid;
        int hr = lin >> 3;
        int m8 = (lin & 7) * 8;
        float v[8];
#pragma unroll
        for (int j = 0; j < 8; j++) {
            v[j] = ts[m8 + j][hr];
        }
        uint4 u;
        pack8_plain(v, u);
        *(uint4*)(xt16 + off + (size_t)(h0 + hr) * 512 + m0 + m8) = u;
    }
}

/* ------------------------------------------------------------------ */
/* Prep 2: Wq/Wk -> transposed plain fp16 (wt16). grid (8,8,2).        */
/* ------------------------------------------------------------------ */
__global__ __launch_bounds__(256) void prep_wt(const float* __restrict__ Wq,
                                               const float* __restrict__ Wk) {
    __shared__ float ts[64][65];
    const int tid = threadIdx.x;
    const int k0 = blockIdx.y * 64;
    const int n0 = blockIdx.x * 64;
    const float* src = (blockIdx.z ? Wk : Wq) + (size_t)k0 * 512 + n0;
    const size_t dstoff = (size_t)blockIdx.z * 262144;

#pragma unroll
    for (int i = 0; i < 4; i++) {
        int lin = i * 256 + tid;
        int r = lin >> 4;
        int c4 = (lin & 15) * 4;
        float4 v = *(const float4*)(src + (size_t)r * 512 + c4);
        ts[r][c4 + 0] = v.x;
        ts[r][c4 + 1] = v.y;
        ts[r][c4 + 2] = v.z;
        ts[r][c4 + 3] = v.w;
    }
    __syncthreads();

#pragma unroll
    for (int i = 0; i < 2; i++) {
        int lin = i * 256 + tid;
        int nr = lin >> 3;
        int k8 = (lin & 7) * 8;
        float v[8];
#pragma unroll
        for (int j = 0; j < 8; j++) {
            v[j] = ts[k8 + j][nr];
        }
        uint4 u;
        pack8_plain(v, u);
        *(uint4*)(wt16 + dstoff + (size_t)(n0 + nr) * 512 + k0 + k8) = u;
    }
}

/* ------------------------------------------------------------------ */
/* Generic plain-fp16 GEMM body: 3-stage cp.async pipeline, GBK=64,    */
/* 512 threads. Pointer-increment addressing.                          */
/* ------------------------------------------------------------------ */
#define PTILE (128 * GASTR)                  /* elems per array */
#define STAGE_BYTES (2 * PTILE * 2)          /* 36864 */
#define GSMEM_BYTES (GSTAGES * STAGE_BYTES)  /* 110592 */

template <bool SUMS>
__device__ __forceinline__ void gemm128_body(
    const uint16_t* __restrict__ A, const uint16_t* __restrict__ B,
    uint32_t s0addr, int tid, int wm, int wn, int lane, float acc[2][4][4],
    float sacc[2][4]) {
    const int trow = tid >> 3;
    const int tcol = (tid & 7) * 8;
    const uint16_t* pa = A + (size_t)trow * 512 + tcol;
    const uint16_t* pb = B + (size_t)trow * 512 + tcol;
    const uint32_t soff = (uint32_t)(trow * GASTR + tcol) * 2;

#pragma unroll
    for (int s = 0; s < GSTAGES - 1; s++) {
        uint32_t sb = s0addr + s * STAGE_BYTES + soff;
#pragma unroll
        for (int i = 0; i < 2; i++) {
            cpa16(sb + i * (64 * GASTR * 2), pa + i * (64 * 512));
            cpa16(sb + PTILE * 2 + i * (64 * GASTR * 2), pb + i * (64 * 512));
        }
        cpa_commit();
        pa += GBK;
        pb += GBK;
    }

    int cur = 0;
    int nxt = 2;
    for (int c = 0; c < GNITER; c++) {
        cpa_wait<1>();
        __syncthreads();
        if (c + GSTAGES - 1 < GNITER) {
            uint32_t sb = s0addr + nxt * STAGE_BYTES + soff;
#pragma unroll
            for (int i = 0; i < 2; i++) {
                cpa16(sb + i * (64 * GASTR * 2), pa + i * (64 * 512));
                cpa16(sb + PTILE * 2 + i * (64 * GASTR * 2), pb + i * (64 * 512));
            }
            pa += GBK;
            pb += GBK;
        }
        cpa_commit();
        uint32_t sb = s0addr + cur * STAGE_BYTES;
        compute128_h<SUMS>(sb, sb + PTILE * 2, wm, wn, lane, acc, sacc);
        cur = (cur == 2) ? 0 : cur + 1;
        nxt = (nxt == 2) ? 0 : nxt + 1;
    }
}

/* ------------------------------------------------------------------ */
/* Kernel: q/k projections. grid (4, 128, 2), 512 thr, 2 CTAs/SM.      */
/* ------------------------------------------------------------------ */
__global__ __launch_bounds__(512, 2) void proj_kernel(
    const float* __restrict__ bq, const float* __restrict__ bk) {
    extern __shared__ uint16_t dynsm[];

    const int tid = threadIdx.x;
    const int lane = tid & 31;
    const int wid = tid >> 5;
    const int wm = wid & 3;
    const int wn = wid >> 2;
    const int z = blockIdx.z;
    const int row0 = blockIdx.y * 128;
    const int col0 = blockIdx.x * 128;

    const uint16_t* A = xd16 + (size_t)row0 * 512;
    const uint16_t* B = wt16 + (size_t)z * 262144 + (size_t)col0 * 512;

    float acc[2][4][4] = {};
    gemm128_body<false>(A, B, sptr(dynsm), tid, wm, wn, lane, acc, nullptr);

    const float* bias = z ? bk : bq;
    uint16_t* O = z ? k16 : q16;
    const int g = lane >> 2;
    const int tg2 = (lane & 3) * 2;
#pragma unroll
    for (int mt = 0; mt < 2; mt++) {
        int r = row0 + wm * 32 + mt * 16 + g;
#pragma unroll
        for (int nt = 0; nt < 4; nt++) {
            int c = col0 + wn * 32 + nt * 8 + tg2;
            float2 bv = *(const float2*)(bias + c);
            __half2 p0 = __floats2half2_rn(acc[mt][nt][0] + bv.x, acc[mt][nt][1] + bv.y);
            __half2 p1 = __floats2half2_rn(acc[mt][nt][2] + bv.x, acc[mt][nt][3] + bv.y);
            *(uint32_t*)(O + (size_t)r * 512 + c) = *reinterpret_cast<uint32_t*>(&p0);
            *(uint32_t*)(O + (size_t)(r + 8) * 512 + c) = *reinterpret_cast<uint32_t*>(&p1);
        }
    }
}

/* ------------------------------------------------------------------ */
/* Kernel: scores -> at16 = exp(sigmoid(q k^T / sqrt(512))) fp16.      */
/* ------------------------------------------------------------------ */
__device__ __forceinline__ float esig(float x, float scale) {
    return __expf(__fdividef(1.f, 1.f + __expf(-x * scale)));
}

__global__ __launch_bounds__(512, 2) void scores_kernel() {
    extern __shared__ uint16_t dynsm[];

    const int tid = threadIdx.x;
    const int lane = tid & 31;
    const int wid = tid >> 5;
    const int wm = wid & 3;
    const int wn = wid >> 2;
    const int b = blockIdx.z;
    const int row0 = blockIdx.y * 128;
    const int col0 = blockIdx.x * 128;

    const uint16_t* A = q16 + ((size_t)b * 512 + row0) * 512;
    const uint16_t* B = k16 + ((size_t)b * 512 + col0) * 512;

    float acc[2][4][4] = {};
    gemm128_body<false>(A, B, sptr(dynsm), tid, wm, wn, lane, acc, nullptr);

    const float scale = 0.04419417382415922f; /* 1/sqrt(512) */
    uint16_t* E = at16 + (size_t)b * 262144;
    const int g = lane >> 2;
    const int tg2 = (lane & 3) * 2;
#pragma unroll
    for (int mt = 0; mt < 2; mt++) {
        int r = row0 + wm * 32 + mt * 16 + g;
#pragma unroll
        for (int nt = 0; nt < 4; nt++) {
            int c = col0 + wn * 32 + nt * 8 + tg2;
            __half2 p0 = __floats2half2_rn(esig(acc[mt][nt][0], scale),
                                           esig(acc[mt][nt][1], scale));
            __half2 p1 = __floats2half2_rn(esig(acc[mt][nt][2], scale),
                                           esig(acc[mt][nt][3], scale));
            *(uint32_t*)(E + (size_t)r * 512 + c) = *reinterpret_cast<uint32_t*>(&p0);
            *(uint32_t*)(E + (size_t)(r + 8) * 512 + c) = *reinterpret_cast<uint32_t*>(&p1);
        }
    }
}

/* ------------------------------------------------------------------ */
/* Kernel: ax = softmax @ x. Row sums via MMA-with-ones in wn==0       */
/* warps; 1/sum shared through smem; every CTA writes its own 128x128  */
/* column quarter of the fp32 attention output. grid (4,4,32).         */
/* ------------------------------------------------------------------ */
__global__ __launch_bounds__(512, 2) void ax_kernel(float* __restrict__ attn) {
    extern __shared__ uint16_t dynsm[];
    __shared__ float rs[128];

    const int tid = threadIdx.x;
    const int lane = tid & 31;
    const int wid = tid >> 5;
    const int wm = wid & 3;
    const int wn = wid >> 2;
    const int b = blockIdx.z;
    const int row0 = blockIdx.y * 128;
    const int col0 = blockIdx.x * 128;

    const uint16_t* A = at16 + ((size_t)b * 512 + row0) * 512;
    const uint16_t* B = xt16 + ((size_t)b * 512 + col0) * 512;

    float acc[2][4][4] = {};
    float sacc[2][4] = {};
    gemm128_body<true>(A, B, sptr(dynsm), tid, wm, wn, lane, acc, sacc);

    const int g = lane >> 2;
    /* wn==0 warps hold complete row sums in sacc[mt][0] (row g) and
       sacc[mt][2] (row g+8); one lane per quad publishes 1/sum.        */
    if (wn == 0 && (lane & 3) == 0) {
#pragma unroll
        for (int mt = 0; mt < 2; mt++) {
            rs[wm * 32 + mt * 16 + g] = 1.f / sacc[mt][0];
            rs[wm * 32 + mt * 16 + g + 8] = 1.f / sacc[mt][2];
        }
    }
    __syncthreads();

    const size_t rowg = (size_t)b * 512;
    const int tg2 = (lane & 3) * 2;
#pragma unroll
    for (int mt = 0; mt < 2; mt++) {
        int rl = wm * 32 + mt * 16 + g;
        int r = row0 + rl;
        float i0 = rs[rl];
        float i1 = rs[rl + 8];
#pragma unroll
        for (int nt = 0; nt < 4; nt++) {
            int c = col0 + wn * 32 + nt * 8 + tg2;
            __half2 p0 = __floats2half2_rn(acc[mt][nt][0] * i0, acc[mt][nt][1] * i0);
            __half2 p1 = __floats2half2_rn(acc[mt][nt][2] * i1, acc[mt][nt][3] * i1);
            *(uint32_t*)(ax16 + (rowg + r) * 512 + c) = *reinterpret_cast<uint32_t*>(&p0);
            *(uint32_t*)(ax16 + (rowg + r + 8) * 512 + c) = *reinterpret_cast<uint32_t*>(&p1);
        }
    }

    /* each CTA writes its own 128x128 fp32 attention quarter */
    {
        const int rl = tid >> 2;           /* 0..127 */
        const int cb = (tid & 3) * 32;     /* local col base: 4 x 32 */
        const float rv = rs[rl];
        const uint16_t* src = at16 + (rowg + row0 + rl) * 512 + col0 + cb;
        float* dst = attn + (size_t)b * 262144 + (size_t)(row0 + rl) * 512 + col0 + cb;
#pragma unroll
        for (int i = 0; i < 8; i++) {
            uint2 u = *(const uint2*)(src + i * 4);
            float2 f0 = __half22float2(*reinterpret_cast<__half2*>(&u.x));
            float2 f1 = __half22float2(*reinterpret_cast<__half2*>(&u.y));
            float4 o;
            o.x = f0.x * rv;
            o.y = f0.y * rv;
            o.z = f1.x * rv;
            o.w = f1.y * rv;
            *(float4*)(dst + i * 4) = o;
        }
    }
}

/* ------------------------------------------------------------------ */
/* Kernel: split-K partials of out = ax.reshape(32,262144) @ Wm.       */
/* (unchanged — measured at the LTS bandwidth cap)                     */
/* ------------------------------------------------------------------ */
#define FAEL (32 * FASTR)              /* A stage elems: [m][k] */
#define FBEL (32 * BN_LD)              /* B stage elems: [k][n] */
#define FSTAGE (FAEL + FBEL)

__global__ __launch_bounds__(256, 2) void final_kernel(const float* __restrict__ Wm) {
    __shared__ alignas(16) uint16_t dsm[2 * FSTAGE];

    const int tid = threadIdx.x;
    const int lane = tid & 31;
    const int wid = tid >> 5;
    const int col0 = blockIdx.x * 128;
    const size_t kbase = (size_t)blockIdx.y * KCHUNK;

    float acc[2][2][4] = {};
    uint2 va;
    float4 vb[4];
    const int am = tid >> 3;
    const int ak = (tid & 7) * 4;
    const int bk_r = tid >> 5;
    const int bn4 = (tid & 31) * 4;

    va = *(const uint2*)(ax16 + (size_t)am * 262144 + kbase + ak);
#pragma unroll
    for (int i = 0; i < 4; i++) {
        vb[i] = *(const float4*)(Wm + (kbase + bk_r + i * 8) * 512 + col0 + bn4);
    }

    auto store_stage = [&](uint16_t* stg) {
        *(uint2*)(stg + am * FASTR + ak) = va;
        uint16_t* bs = stg + FAEL;
#pragma unroll
        for (int i = 0; i < 4; i++) {
            __half2 p0 = __floats2half2_rn(vb[i].x, vb[i].y);
            __half2 p1 = __floats2half2_rn(vb[i].z, vb[i].w);
            uint2 u;
            u.x = *reinterpret_cast<uint32_t*>(&p0);
            u.y = *reinterpret_cast<uint32_t*>(&p1);
            *(uint2*)(bs + (bk_r + i * 8) * BN_LD + bn4) = u;
        }
    };

    store_stage(dsm);
    va = *(const uint2*)(ax16 + (size_t)am * 262144 + kbase + FBK + ak);
#pragma unroll
    for (int i = 0; i < 4; i++) {
        vb[i] = *(const float4*)(Wm + (kbase + FBK + bk_r + i * 8) * 512 + col0 + bn4);
    }
    __syncthreads();

    const int lr = (lane & 7) + ((lane >> 3) & 1) * 8;
    const int lc = (lane >> 4) * 8;
    const int trow = (lane >> 4) * 8 + (lane & 7);
    const int tcol = ((lane >> 3) & 1) * 8;

    for (int k0 = 0; k0 < KCHUNK; k0 += FBK) {
        int cur = (k0 >> 5) & 1;
        if (k0 + FBK < KCHUNK) {
            store_stage(dsm + (cur ^ 1) * FSTAGE);
        }
        if (k0 + 2 * FBK < KCHUNK) {
            va = *(const uint2*)(ax16 + (size_t)am * 262144 + kbase + k0 + 2 * FBK + ak);
#pragma unroll
            for (int i = 0; i < 4; i++) {
                vb[i] = *(const float4*)(Wm + (kbase + k0 + 2 * FBK + bk_r + i * 8) * 512 +
                                         col0 + bn4);
            }
        }
        uint32_t base = sptr(dsm) + cur * FSTAGE * 2;
        uint32_t sA = base;
        uint32_t sB = base + FAEL * 2;
#pragma unroll
        for (int ks = 0; ks < FBK; ks += 16) {
            uint32_t bf[2][2];
            uint32_t offb = (uint32_t)(((ks + trow) * BN_LD + wid * 16 + tcol) * 2);
            uint32_t r0, r1, r2, r3;
            ldsm_x4_trans(r0, r1, r2, r3, sB + offb);
            bf[0][0] = r0;
            bf[1][0] = r1;
            bf[0][1] = r2;
            bf[1][1] = r3;
            uint32_t a[2][4];
#pragma unroll
            for (int mt = 0; mt < 2; mt++) {
                uint32_t offa = (uint32_t)(((mt * 16 + lr) * FASTR + ks + lc) * 2);
                ldsm_x4(a[mt][0], a[mt][1], a[mt][2], a[mt][3], sA + offa);
            }
#pragma unroll
            for (int mt = 0; mt < 2; mt++) {
#pragma unroll
                for (int nt = 0; nt < 2; nt++) {
                    mma_f16(acc[mt][nt], a[mt], bf[nt]);
                }
            }
        }
        __syncthreads();
    }

    const int g = lane >> 2;
    const int tg2 = (lane & 3) * 2;
    float* P = g_part + (size_t)blockIdx.y * 16384;
#pragma unroll
    for (int mt = 0; mt < 2; mt++) {
        int r = mt * 16 + g;
#pragma unroll
        for (int nt = 0; nt < 2; nt++) {
            int c = col0 + wid * 16 + nt * 8 + tg2;
            float2 o0;
            float2 o1;
            o0.x = acc[mt][nt][0];
            o0.y = acc[mt][nt][1];
            o1.x = acc[mt][nt][2];
            o1.y = acc[mt][nt][3];
            *(float2*)(P + (size_t)r * 512 + c) = o0;
            *(float2*)(P + (size_t)(r + 8) * 512 + c) = o1;
        }
    }
}

/* ------------------------------------------------------------------ */
/* Kernel: deterministic split-K reduce + bias. grid 64 x 256.         */
/* ------------------------------------------------------------------ */
__global__ __launch_bounds__(256) void reduce_kernel(float* __restrict__ out,
                                                     const float* __restrict__ bm) {
    const int idx = blockIdx.x * 256 + threadIdx.x;
    const int n = idx & 511;
    float sum = bm[n];
#pragma unroll 8
    for (int s = 0; s < KSPLIT; s++) {
        sum += g_part[(size_t)s * 16384 + idx];
    }
    out[idx] = sum;
}

/* ------------------------------------------------------------------ */
extern "C" void kernel_launch(void* const* d_in, const int* in_sizes, int n_in,
                              void* d_out, int out_size) {
    const float* x = (const float*)d_in[0];
    const float* Wq = (const float*)d_in[1];
    const float* bq = (const float*)d_in[2];
    const float* Wk = (const float*)d_in[3];
    const float* bk = (const float*)d_in[4];
    const float* Wm = (const float*)d_in[5];
    const float* bm = (const float*)d_in[6];

    float* out = (float*)d_out;   /* [32, 512] */
    float* attn = out + 32 * 512; /* [32, 512, 512] */

    cudaFuncSetAttribute(proj_kernel, cudaFuncAttributeMaxDynamicSharedMemorySize,
                         GSMEM_BYTES);
    cudaFuncSetAttribute(scores_kernel, cudaFuncAttributeMaxDynamicSharedMemorySize,
                         GSMEM_BYTES);
    cudaFuncSetAttribute(ax_kernel, cudaFuncAttributeMaxDynamicSharedMemorySize,
                         GSMEM_BYTES);

    prep_x<<<dim3(8, 8, 32), 256>>>(x);
    prep_wt<<<dim3(8, 8, 2), 256>>>(Wq, Wk);
    proj_kernel<<<dim3(4, 128, 2), 512, GSMEM_BYTES>>>(bq, bk);
    scores_kernel<<<dim3(4, 4, 32), 512, GSMEM_BYTES>>>();
    ax_kernel<<<dim3(4, 4, 32), 512, GSMEM_BYTES>>>(attn);
    final_kernel<<<dim3(4, KSPLIT), 256>>>(Wm);
    reduce_kernel<<<64, 256>>>(out, bm);
}

// round 16
// speedup vs baseline: 1.1847x; 1.1170x over previous
#include <cuda_runtime.h>
#include <cuda_fp16.h>
#include <stdint.h>
#include <math.h>

/* GEMM pipeline constants */
#define GBK 64             /* k per slab */
#define GASTR 72           /* padded smem stride (144 B rows) */
#define GNITER 8           /* K=512 / GBK */
#define GSTAGES 3

/* final kernel constants */
#define FBK 32
#define FASTR 40
#define KSPLIT 64
#define KCHUNK 4096
#define BN_LD 136

/* Scratch: __device__ globals (allocation-free rule) */
__device__ uint16_t xd16[32 * 512 * 512];   /* x direct fp16 [b*512+n][h] */
__device__ uint16_t xt16[32 * 512 * 512];   /* x^T fp16 [b][h][m] */
__device__ uint16_t wq16[512 * 512];        /* Wq direct fp16 [h][d] */
__device__ uint16_t wk16[512 * 512];        /* Wk direct fp16 [h][d] */
__device__ uint16_t wpt16[512 * 512];       /* (Wq Wk^T)^T fp16 [j][h] */
__device__ uint16_t v16[32 * 512 * 512];    /* v = x @ W' fp16 */
__device__ uint16_t at16[32 * 512 * 512];   /* exp(sigmoid(scores)) fp16 */
__device__ uint16_t ax16[32 * 512 * 512];   /* softmax @ x, fp16 */
__device__ float g_rinv[32 * 512];          /* per-row 1/sum(exp) */
__device__ float g_wqbk[512];               /* Wq @ bk */
__device__ float g_wkbq[512];               /* Wk @ bq */
__device__ float g_c0[1];                   /* bq . bk */
__device__ float g_r1[32 * 512];            /* x . (Wq bk) per row */
__device__ float g_r2[32 * 512];            /* x . (Wk bq) per row */
__device__ float g_part[KSPLIT * 32 * 512];

/* ------------------------------------------------------------------ */
/* Helpers                                                             */
/* ------------------------------------------------------------------ */
__device__ __forceinline__ uint32_t sptr(const void* p) {
    return (uint32_t)__cvta_generic_to_shared(p);
}

__device__ __forceinline__ void ldsm_x4(uint32_t& r0, uint32_t& r1,
                                        uint32_t& r2, uint32_t& r3,
                                        uint32_t addr) {
    asm volatile("ldmatrix.sync.aligned.m8n8.x4.shared.b16 {%0,%1,%2,%3}, [%4];"
                 : "=r"(r0), "=r"(r1), "=r"(r2), "=r"(r3)
                 : "r"(addr));
}

__device__ __forceinline__ void ldsm_x4_trans(uint32_t& r0, uint32_t& r1,
                                              uint32_t& r2, uint32_t& r3,
                                              uint32_t addr) {
    asm volatile("ldmatrix.sync.aligned.m8n8.x4.trans.shared.b16 {%0,%1,%2,%3}, [%4];"
                 : "=r"(r0), "=r"(r1), "=r"(r2), "=r"(r3)
                 : "r"(addr));
}

__device__ __forceinline__ void mma_f16(float* c, const uint32_t* a,
                                        const uint32_t* b) {
    asm volatile(
        "mma.sync.aligned.m16n8k16.row.col.f32.f16.f16.f32 "
        "{%0,%1,%2,%3}, {%4,%5,%6,%7}, {%8,%9}, {%0,%1,%2,%3};"
        : "+f"(c[0]), "+f"(c[1]), "+f"(c[2]), "+f"(c[3])
        : "r"(a[0]), "r"(a[1]), "r"(a[2]), "r"(a[3]),
          "r"(b[0]), "r"(b[1]));
}

__device__ __forceinline__ void cpa16(uint32_t dst, const void* src) {
    asm volatile("cp.async.cg.shared.global [%0], [%1], 16;"
                 :: "r"(dst), "l"(src) : "memory");
}
__device__ __forceinline__ void cpa_commit() {
    asm volatile("cp.async.commit_group;" ::: "memory");
}
template <int N>
__device__ __forceinline__ void cpa_wait() {
    asm volatile("cp.async.wait_group %0;" :: "n"(N) : "memory");
}

__device__ __forceinline__ uint16_t h1(float v) {
    __half h = __float2half_rn(v);
    return *reinterpret_cast<uint16_t*>(&h);
}

__device__ __forceinline__ void pack8_plain(const float* v, uint4& u) {
    uint16_t h[8];
#pragma unroll
    for (int j = 0; j < 8; j++) {
        h[j] = h1(v[j]);
    }
    u.x = (uint32_t)h[0] | ((uint32_t)h[1] << 16);
    u.y = (uint32_t)h[2] | ((uint32_t)h[3] << 16);
    u.z = (uint32_t)h[4] | ((uint32_t)h[5] << 16);
    u.w = (uint32_t)h[6] | ((uint32_t)h[7] << 16);
}

/* ------------------------------------------------------------------ */
/* Compute: one GBK=64 slab, 128x128 CTA tile, 16 warps (wm 4 x wn 4), */
/* warp tile 32x32, acc[2][4][4] = 32 regs.                            */
/* ------------------------------------------------------------------ */
__device__ __forceinline__ void compute128_h(uint32_t sA, uint32_t sB,
                                             int wm, int wn, int lane,
                                             float acc[2][4][4]) {
    const int lr = (lane & 7) + ((lane >> 3) & 1) * 8;
    const int lc = (lane >> 4) * 8;

#pragma unroll
    for (int h = 0; h < 4; h++) {
        uint32_t b[4][2];
#pragma unroll
        for (int p = 0; p < 2; p++) {
            uint32_t off = (uint32_t)(((wn * 32 + p * 16 + lr) * GASTR + h * 16 + lc) * 2);
            uint32_t r0, r1, r2, r3;
            ldsm_x4(r0, r1, r2, r3, sB + off);
            b[2 * p][0] = r0;
            b[2 * p][1] = r2;
            b[2 * p + 1][0] = r1;
            b[2 * p + 1][1] = r3;
        }
        uint32_t a[2][4];
#pragma unroll
        for (int mt = 0; mt < 2; mt++) {
            uint32_t off = (uint32_t)(((wm * 32 + mt * 16 + lr) * GASTR + h * 16 + lc) * 2);
            ldsm_x4(a[mt][0], a[mt][1], a[mt][2], a[mt][3], sA + off);
        }
#pragma unroll
        for (int mt = 0; mt < 2; mt++) {
#pragma unroll
            for (int nt = 0; nt < 4; nt++) {
                mma_f16(acc[mt][nt], a[mt], b[nt]);
            }
        }
    }
}

/* ------------------------------------------------------------------ */
/* Prep 1: x -> direct fp16 (xd16) AND transposed fp16 (xt16).         */
/* ------------------------------------------------------------------ */
__global__ __launch_bounds__(256) void prep_x(const float* __restrict__ x) {
    __shared__ float ts[64][65];
    const int tid = threadIdx.x;
    const int m0 = blockIdx.y * 64;
    const int h0 = blockIdx.x * 64;
    const size_t off = (size_t)blockIdx.z * 262144;
    const float* src = x + off + (size_t)m0 * 512 + h0;

#pragma unroll
    for (int i = 0; i < 4; i++) {
        int lin = i * 256 + tid;
        int r = lin >> 4;
        int c4 = (lin & 15) * 4;
        float4 v = *(const float4*)(src + (size_t)r * 512 + c4);
        ts[r][c4 + 0] = v.x;
        ts[r][c4 + 1] = v.y;
        ts[r][c4 + 2] = v.z;
        ts[r][c4 + 3] = v.w;
    }
    __syncthreads();

#pragma unroll
    for (int i = 0; i < 2; i++) {
        int lin = i * 256 + tid;
        int r = lin >> 3;
        int c8 = (lin & 7) * 8;
        float v[8];
#pragma unroll
        for (int j = 0; j < 8; j++) {
            v[j] = ts[r][c8 + j];
        }
        uint4 u;
        pack8_plain(v, u);
        *(uint4*)(xd16 + off + (size_t)(m0 + r) * 512 + h0 + c8) = u;
    }
#pragma unroll
    for (int i = 0; i < 2; i++) {
        int lin = i * 256 + tid;
        int hr = lin >> 3;
        int m8 = (lin & 7) * 8;
        float v[8];
#pragma unroll
        for (int j = 0; j < 8; j++) {
            v[j] = ts[m8 + j][hr];
        }
        uint4 u;
        pack8_plain(v, u);
        *(uint4*)(xt16 + off + (size_t)(h0 + hr) * 512 + m0 + m8) = u;
    }
}

/* ------------------------------------------------------------------ */
/* Prep 2: Wq/Wk -> direct fp16 (wq16/wk16). grid (128, 2) x 256.      */
/* ------------------------------------------------------------------ */
__global__ __launch_bounds__(256) void prep_w(const float* __restrict__ Wq,
                                              const float* __restrict__ Wk) {
    const float* src = blockIdx.y ? Wk : Wq;
    uint16_t* dst = blockIdx.y ? wk16 : wq16;
    int lin = blockIdx.x * 256 + threadIdx.x;
    size_t e = (size_t)lin * 8;
    float v[8];
    float4 a = *(const float4*)(src + e);
    float4 b = *(const float4*)(src + e + 4);
    v[0] = a.x; v[1] = a.y; v[2] = a.z; v[3] = a.w;
    v[4] = b.x; v[5] = b.y; v[6] = b.z; v[7] = b.w;
    uint4 u;
    pack8_plain(v, u);
    *(uint4*)(dst + e) = u;
}

/* ------------------------------------------------------------------ */
/* Generic plain-fp16 GEMM body: 3-stage cp.async pipeline, GBK=64,    */
/* 512 threads. Pointer-increment addressing.                          */
/* ------------------------------------------------------------------ */
#define PTILE (128 * GASTR)
#define STAGE_BYTES (2 * PTILE * 2)
#define GSMEM_BYTES (GSTAGES * STAGE_BYTES)   /* 110592 */

__device__ __forceinline__ void gemm128_body(
    const uint16_t* __restrict__ A, const uint16_t* __restrict__ B,
    uint32_t s0addr, int tid, int wm, int wn, int lane, float acc[2][4][4]) {
    const int trow = tid >> 3;
    const int tcol = (tid & 7) * 8;
    const uint16_t* pa = A + (size_t)trow * 512 + tcol;
    const uint16_t* pb = B + (size_t)trow * 512 + tcol;
    const uint32_t soff = (uint32_t)(trow * GASTR + tcol) * 2;

#pragma unroll
    for (int s = 0; s < GSTAGES - 1; s++) {
        uint32_t sb = s0addr + s * STAGE_BYTES + soff;
#pragma unroll
        for (int i = 0; i < 2; i++) {
            cpa16(sb + i * (64 * GASTR * 2), pa + i * (64 * 512));
            cpa16(sb + PTILE * 2 + i * (64 * GASTR * 2), pb + i * (64 * 512));
        }
        cpa_commit();
        pa += GBK;
        pb += GBK;
    }

    int cur = 0;
    int nxt = 2;
    for (int c = 0; c < GNITER; c++) {
        cpa_wait<1>();
        __syncthreads();
        if (c + GSTAGES - 1 < GNITER) {
            uint32_t sb = s0addr + nxt * STAGE_BYTES + soff;
#pragma unroll
            for (int i = 0; i < 2; i++) {
                cpa16(sb + i * (64 * GASTR * 2), pa + i * (64 * 512));
                cpa16(sb + PTILE * 2 + i * (64 * GASTR * 2), pb + i * (64 * 512));
            }
            pa += GBK;
            pb += GBK;
        }
        cpa_commit();
        uint32_t sb = s0addr + cur * STAGE_BYTES;
        compute128_h(sb, sb + PTILE * 2, wm, wn, lane, acc);
        cur = (cur == 2) ? 0 : cur + 1;
        nxt = (nxt == 2) ? 0 : nxt + 1;
    }
}

/* ------------------------------------------------------------------ */
/* Kernel: W'^T = (Wq @ Wk^T)^T -> wpt16. grid (4,4), 512 thr.         */
/* A = wq16 direct, B = wk16 direct. Epilogue stores transposed.       */
/* ------------------------------------------------------------------ */
__global__ __launch_bounds__(512, 2) void wprime_kernel() {
    extern __shared__ uint16_t dynsm[];

    const int tid = threadIdx.x;
    const int lane = tid & 31;
    const int wid = tid >> 5;
    const int wm = wid & 3;
    const int wn = wid >> 2;
    const int row0 = blockIdx.y * 128;
    const int col0 = blockIdx.x * 128;

    float acc[2][4][4] = {};
    gemm128_body(wq16 + (size_t)row0 * 512, wk16 + (size_t)col0 * 512,
                 sptr(dynsm), tid, wm, wn, lane, acc);

    const int g = lane >> 2;
    const int tg2 = (lane & 3) * 2;
#pragma unroll
    for (int mt = 0; mt < 2; mt++) {
        int r = row0 + wm * 32 + mt * 16 + g;
#pragma unroll
        for (int nt = 0; nt < 4; nt++) {
            int c = col0 + wn * 32 + nt * 8 + tg2;
            wpt16[(size_t)c * 512 + r] = h1(acc[mt][nt][0]);
            wpt16[(size_t)(c + 1) * 512 + r] = h1(acc[mt][nt][1]);
            wpt16[(size_t)c * 512 + r + 8] = h1(acc[mt][nt][2]);
            wpt16[(size_t)(c + 1) * 512 + r + 8] = h1(acc[mt][nt][3]);
        }
    }
}

/* ------------------------------------------------------------------ */
/* Kernel: bias vectors. blocks 0..63: warp per h row computes         */
/* g_wqbk[h] = Wq[h,:].bk and g_wkbq[h] = Wk[h,:].bq. block 64: c0.    */
/* ------------------------------------------------------------------ */
__global__ __launch_bounds__(256) void vecs_kernel(
    const float* __restrict__ Wq, const float* __restrict__ bk,
    const float* __restrict__ Wk, const float* __restrict__ bq) {
    const int w = threadIdx.x >> 5;
    const int lane = threadIdx.x & 31;
    if (blockIdx.x < 64) {
        const int h = blockIdx.x * 8 + w;
        float s1 = 0.f;
        float s2 = 0.f;
#pragma unroll
        for (int i = 0; i < 16; i++) {
            int d = lane + i * 32;
            s1 += Wq[(size_t)h * 512 + d] * bk[d];
            s2 += Wk[(size_t)h * 512 + d] * bq[d];
        }
#pragma unroll
        for (int o = 16; o > 0; o >>= 1) {
            s1 += __shfl_xor_sync(0xffffffffu, s1, o);
            s2 += __shfl_xor_sync(0xffffffffu, s2, o);
        }
        if (lane == 0) {
            g_wqbk[h] = s1;
            g_wkbq[h] = s2;
        }
    } else if (w == 0) {
        float s = 0.f;
#pragma unroll
        for (int i = 0; i < 16; i++) {
            int d = lane + i * 32;
            s += bq[d] * bk[d];
        }
#pragma unroll
        for (int o = 16; o > 0; o >>= 1) {
            s += __shfl_xor_sync(0xffffffffu, s, o);
        }
        if (lane == 0) {
            g_c0[0] = s;
        }
    }
}

/* ------------------------------------------------------------------ */
/* Kernel: r1[n] = x[n].wqbk, r2[n] = x[n].wkbq. Warp per row,         */
/* reads xd16. grid 2048 x 256.                                        */
/* ------------------------------------------------------------------ */
__global__ __launch_bounds__(256) void r_kernel() {
    const int w = threadIdx.x >> 5;
    const int lane = threadIdx.x & 31;
    const size_t row = (size_t)blockIdx.x * 8 + w;
    const uint16_t* p = xd16 + row * 512;

    float s1 = 0.f;
    float s2 = 0.f;
#pragma unroll
    for (int i = 0; i < 4; i++) {
        int cb = i * 128 + lane * 4;
        uint2 u = *(const uint2*)(p + cb);
        float2 f0 = __half22float2(*reinterpret_cast<__half2*>(&u.x));
        float2 f1 = __half22float2(*reinterpret_cast<__half2*>(&u.y));
        s1 += f0.x * g_wqbk[cb] + f0.y * g_wqbk[cb + 1] +
              f1.x * g_wqbk[cb + 2] + f1.y * g_wqbk[cb + 3];
        s2 += f0.x * g_wkbq[cb] + f0.y * g_wkbq[cb + 1] +
              f1.x * g_wkbq[cb + 2] + f1.y * g_wkbq[cb + 3];
    }
#pragma unroll
    for (int o = 16; o > 0; o >>= 1) {
        s1 += __shfl_xor_sync(0xffffffffu, s1, o);
        s2 += __shfl_xor_sync(0xffffffffu, s2, o);
    }
    if (lane == 0) {
        g_r1[row] = s1;
        g_r2[row] = s2;
    }
}

/* ------------------------------------------------------------------ */
/* Kernel: v = x @ W'. grid (4, 128), 512 thr, 2 CTAs/SM.              */
/* ------------------------------------------------------------------ */
__global__ __launch_bounds__(512, 2) void v_kernel() {
    extern __shared__ uint16_t dynsm[];

    const int tid = threadIdx.x;
    const int lane = tid & 31;
    const int wid = tid >> 5;
    const int wm = wid & 3;
    const int wn = wid >> 2;
    const int row0 = blockIdx.y * 128;
    const int col0 = blockIdx.x * 128;

    const uint16_t* A = xd16 + (size_t)row0 * 512;
    const uint16_t* B = wpt16 + (size_t)col0 * 512;

    float acc[2][4][4] = {};
    gemm128_body(A, B, sptr(dynsm), tid, wm, wn, lane, acc);

    const int g = lane >> 2;
    const int tg2 = (lane & 3) * 2;
#pragma unroll
    for (int mt = 0; mt < 2; mt++) {
        int r = row0 + wm * 32 + mt * 16 + g;
#pragma unroll
        for (int nt = 0; nt < 4; nt++) {
            int c = col0 + wn * 32 + nt * 8 + tg2;
            __half2 p0 = __floats2half2_rn(acc[mt][nt][0], acc[mt][nt][1]);
            __half2 p1 = __floats2half2_rn(acc[mt][nt][2], acc[mt][nt][3]);
            *(uint32_t*)(v16 + (size_t)r * 512 + c) = *reinterpret_cast<uint32_t*>(&p0);
            *(uint32_t*)(v16 + (size_t)(r + 8) * 512 + c) = *reinterpret_cast<uint32_t*>(&p1);
        }
    }
}

/* ------------------------------------------------------------------ */
/* Kernel: scores -> at16 = exp(sigmoid((v x^T + r1 + r2 + c0)/sq)).   */
/* A = v16, B = xd16. grid (4,4,32), 512 thr.                          */
/* ------------------------------------------------------------------ */
__device__ __forceinline__ float esig(float x, float scale) {
    return __expf(__fdividef(1.f, 1.f + __expf(-x * scale)));
}

__global__ __launch_bounds__(512, 2) void scores_kernel() {
    extern __shared__ uint16_t dynsm[];

    const int tid = threadIdx.x;
    const int lane = tid & 31;
    const int wid = tid >> 5;
    const int wm = wid & 3;
    const int wn = wid >> 2;
    const int b = blockIdx.z;
    const int row0 = blockIdx.y * 128;
    const int col0 = blockIdx.x * 128;

    const uint16_t* A = v16 + ((size_t)b * 512 + row0) * 512;
    const uint16_t* B = xd16 + ((size_t)b * 512 + col0) * 512;

    float acc[2][4][4] = {};
    gemm128_body(A, B, sptr(dynsm), tid, wm, wn, lane, acc);

    const float scale = 0.04419417382415922f; /* 1/sqrt(512) */
    const float c0v = g_c0[0];
    uint16_t* E = at16 + (size_t)b * 262144;
    const int g = lane >> 2;
    const int tg2 = (lane & 3) * 2;
#pragma unroll
    for (int mt = 0; mt < 2; mt++) {
        int r = row0 + wm * 32 + mt * 16 + g;
        float r1a = g_r1[(size_t)b * 512 + r] + c0v;
        float r1b = g_r1[(size_t)b * 512 + r + 8] + c0v;
#pragma unroll
        for (int nt = 0; nt < 4; nt++) {
            int c = col0 + wn * 32 + nt * 8 + tg2;
            float2 r2v = *(const float2*)(g_r2 + (size_t)b * 512 + c);
            __half2 p0 = __floats2half2_rn(
                esig(acc[mt][nt][0] + r1a + r2v.x, scale),
                esig(acc[mt][nt][1] + r1a + r2v.y, scale));
            __half2 p1 = __floats2half2_rn(
                esig(acc[mt][nt][2] + r1b + r2v.x, scale),
                esig(acc[mt][nt][3] + r1b + r2v.y, scale));
            *(uint32_t*)(E + (size_t)r * 512 + c) = *reinterpret_cast<uint32_t*>(&p0);
            *(uint32_t*)(E + (size_t)(r + 8) * 512 + c) = *reinterpret_cast<uint32_t*>(&p1);
        }
    }
}

/* ------------------------------------------------------------------ */
/* Kernel: warp-per-row rowsum. Reads at16, writes normalized fp32     */
/* attn and g_rinv. grid 2048 x 256.                                   */
/* ------------------------------------------------------------------ */
__global__ __launch_bounds__(256) void rowsum_kernel(float* __restrict__ attn) {
    const int w = threadIdx.x >> 5;
    const int lane = threadIdx.x & 31;
    const size_t row = (size_t)blockIdx.x * 8 + w;
    const size_t base = row * 512;

    uint2 u[4];
#pragma unroll
    for (int i = 0; i < 4; i++) {
        u[i] = *(const uint2*)(at16 + base + i * 128 + lane * 4);
    }
    float e[16];
    float s = 0.f;
#pragma unroll
    for (int i = 0; i < 4; i++) {
        __half2 h0 = *reinterpret_cast<__half2*>(&u[i].x);
        __half2 h1v = *reinterpret_cast<__half2*>(&u[i].y);
        float2 f0 = __half22float2(h0);
        float2 f1 = __half22float2(h1v);
        e[i * 4 + 0] = f0.x;
        e[i * 4 + 1] = f0.y;
        e[i * 4 + 2] = f1.x;
        e[i * 4 + 3] = f1.y;
        s += f0.x + f0.y + f1.x + f1.y;
    }
#pragma unroll
    for (int o = 16; o > 0; o >>= 1) {
        s += __shfl_xor_sync(0xffffffffu, s, o);
    }
    const float inv = 1.f / s;
    if (lane == 0) {
        g_rinv[row] = inv;
    }
#pragma unroll
    for (int i = 0; i < 4; i++) {
        float4 o;
        o.x = e[i * 4 + 0] * inv;
        o.y = e[i * 4 + 1] * inv;
        o.z = e[i * 4 + 2] * inv;
        o.w = e[i * 4 + 3] * inv;
        *(float4*)(attn + base + i * 128 + lane * 4) = o;
    }
}

/* ------------------------------------------------------------------ */
/* Kernel: ax = softmax @ x via exp-A GEMM + per-row 1/sum epilogue.   */
/* grid (4,4,32), 512 thr.                                             */
/* ------------------------------------------------------------------ */
__global__ __launch_bounds__(512, 2) void ax_kernel() {
    extern __shared__ uint16_t dynsm[];

    const int tid = threadIdx.x;
    const int lane = tid & 31;
    const int wid = tid >> 5;
    const int wm = wid & 3;
    const int wn = wid >> 2;
    const int b = blockIdx.z;
    const int row0 = blockIdx.y * 128;
    const int col0 = blockIdx.x * 128;

    const uint16_t* A = at16 + ((size_t)b * 512 + row0) * 512;
    const uint16_t* B = xt16 + ((size_t)b * 512 + col0) * 512;

    float acc[2][4][4] = {};
    gemm128_body(A, B, sptr(dynsm), tid, wm, wn, lane, acc);

    const size_t rowg = (size_t)b * 512;
    const int g = lane >> 2;
    const int tg2 = (lane & 3) * 2;
#pragma unroll
    for (int mt = 0; mt < 2; mt++) {
        int r = row0 + wm * 32 + mt * 16 + g;
        float i0 = g_rinv[rowg + r];
        float i1 = g_rinv[rowg + r + 8];
#pragma unroll
        for (int nt = 0; nt < 4; nt++) {
            int c = col0 + wn * 32 + nt * 8 + tg2;
            __half2 p0 = __floats2half2_rn(acc[mt][nt][0] * i0, acc[mt][nt][1] * i0);
            __half2 p1 = __floats2half2_rn(acc[mt][nt][2] * i1, acc[mt][nt][3] * i1);
            *(uint32_t*)(ax16 + (rowg + r) * 512 + c) = *reinterpret_cast<uint32_t*>(&p0);
            *(uint32_t*)(ax16 + (rowg + r + 8) * 512 + c) = *reinterpret_cast<uint32_t*>(&p1);
        }
    }
}

/* ------------------------------------------------------------------ */
/* Kernel: split-K partials of out = ax.reshape(32,262144) @ Wm.       */
/* (unchanged — measured at the LTS bandwidth cap)                     */
/* ------------------------------------------------------------------ */
#define FAEL (32 * FASTR)
#define FBEL (32 * BN_LD)
#define FSTAGE (FAEL + FBEL)

__global__ __launch_bounds__(256, 2) void final_kernel(const float* __restrict__ Wm) {
    __shared__ alignas(16) uint16_t dsm[2 * FSTAGE];

    const int tid = threadIdx.x;
    const int lane = tid & 31;
    const int wid = tid >> 5;
    const int col0 = blockIdx.x * 128;
    const size_t kbase = (size_t)blockIdx.y * KCHUNK;

    float acc[2][2][4] = {};
    uint2 va;
    float4 vb[4];
    const int am = tid >> 3;
    const int ak = (tid & 7) * 4;
    const int bk_r = tid >> 5;
    const int bn4 = (tid & 31) * 4;

    va = *(const uint2*)(ax16 + (size_t)am * 262144 + kbase + ak);
#pragma unroll
    for (int i = 0; i < 4; i++) {
        vb[i] = *(const float4*)(Wm + (kbase + bk_r + i * 8) * 512 + col0 + bn4);
    }

    auto store_stage = [&](uint16_t* stg) {
        *(uint2*)(stg + am * FASTR + ak) = va;
        uint16_t* bs = stg + FAEL;
#pragma unroll
        for (int i = 0; i < 4; i++) {
            __half2 p0 = __floats2half2_rn(vb[i].x, vb[i].y);
            __half2 p1 = __floats2half2_rn(vb[i].z, vb[i].w);
            uint2 u;
            u.x = *reinterpret_cast<uint32_t*>(&p0);
            u.y = *reinterpret_cast<uint32_t*>(&p1);
            *(uint2*)(bs + (bk_r + i * 8) * BN_LD + bn4) = u;
        }
    };

    store_stage(dsm);
    va = *(const uint2*)(ax16 + (size_t)am * 262144 + kbase + FBK + ak);
#pragma unroll
    for (int i = 0; i < 4; i++) {
        vb[i] = *(const float4*)(Wm + (kbase + FBK + bk_r + i * 8) * 512 + col0 + bn4);
    }
    __syncthreads();

    const int lr = (lane & 7) + ((lane >> 3) & 1) * 8;
    const int lc = (lane >> 4) * 8;
    const int trow = (lane >> 4) * 8 + (lane & 7);
    const int tcol = ((lane >> 3) & 1) * 8;

    for (int k0 = 0; k0 < KCHUNK; k0 += FBK) {
        int cur = (k0 >> 5) & 1;
        if (k0 + FBK < KCHUNK) {
            store_stage(dsm + (cur ^ 1) * FSTAGE);
        }
        if (k0 + 2 * FBK < KCHUNK) {
            va = *(const uint2*)(ax16 + (size_t)am * 262144 + kbase + k0 + 2 * FBK + ak);
#pragma unroll
            for (int i = 0; i < 4; i++) {
                vb[i] = *(const float4*)(Wm + (kbase + k0 + 2 * FBK + bk_r + i * 8) * 512 +
                                         col0 + bn4);
            }
        }
        uint32_t base = sptr(dsm) + cur * FSTAGE * 2;
        uint32_t sA = base;
        uint32_t sB = base + FAEL * 2;
#pragma unroll
        for (int ks = 0; ks < FBK; ks += 16) {
            uint32_t bf[2][2];
            uint32_t offb = (uint32_t)(((ks + trow) * BN_LD + wid * 16 + tcol) * 2);
            uint32_t r0, r1, r2, r3;
            ldsm_x4_trans(r0, r1, r2, r3, sB + offb);
            bf[0][0] = r0;
            bf[1][0] = r1;
            bf[0][1] = r2;
            bf[1][1] = r3;
            uint32_t a[2][4];
#pragma unroll
            for (int mt = 0; mt < 2; mt++) {
                uint32_t offa = (uint32_t)(((mt * 16 + lr) * FASTR + ks + lc) * 2);
                ldsm_x4(a[mt][0], a[mt][1], a[mt][2], a[mt][3], sA + offa);
            }
#pragma unroll
            for (int mt = 0; mt < 2; mt++) {
#pragma unroll
                for (int nt = 0; nt < 2; nt++) {
                    mma_f16(acc[mt][nt], a[mt], bf[nt]);
                }
            }
        }
        __syncthreads();
    }

    const int g = lane >> 2;
    const int tg2 = (lane & 3) * 2;
    float* P = g_part + (size_t)blockIdx.y * 16384;
#pragma unroll
    for (int mt = 0; mt < 2; mt++) {
        int r = mt * 16 + g;
#pragma unroll
        for (int nt = 0; nt < 2; nt++) {
            int c = col0 + wid * 16 + nt * 8 + tg2;
            float2 o0;
            float2 o1;
            o0.x = acc[mt][nt][0];
            o0.y = acc[mt][nt][1];
            o1.x = acc[mt][nt][2];
            o1.y = acc[mt][nt][3];
            *(float2*)(P + (size_t)r * 512 + c) = o0;
            *(float2*)(P + (size_t)(r + 8) * 512 + c) = o1;
        }
    }
}

/* ------------------------------------------------------------------ */
/* Kernel: deterministic split-K reduce + bias. grid 64 x 256.         */
/* ------------------------------------------------------------------ */
__global__ __launch_bounds__(256) void reduce_kernel(float* __restrict__ out,
                                                     const float* __restrict__ bm) {
    const int idx = blockIdx.x * 256 + threadIdx.x;
    const int n = idx & 511;
    float sum = bm[n];
#pragma unroll 8
    for (int s = 0; s < KSPLIT; s++) {
        sum += g_part[(size_t)s * 16384 + idx];
    }
    out[idx] = sum;
}

/* ------------------------------------------------------------------ */
extern "C" void kernel_launch(void* const* d_in, const int* in_sizes, int n_in,
                              void* d_out, int out_size) {
    const float* x = (const float*)d_in[0];
    const float* Wq = (const float*)d_in[1];
    const float* bq = (const float*)d_in[2];
    const float* Wk = (const float*)d_in[3];
    const float* bk = (const float*)d_in[4];
    const float* Wm = (const float*)d_in[5];
    const float* bm = (const float*)d_in[6];

    float* out = (float*)d_out;   /* [32, 512] */
    float* attn = out + 32 * 512; /* [32, 512, 512] */

    cudaFuncSetAttribute(wprime_kernel, cudaFuncAttributeMaxDynamicSharedMemorySize,
                         GSMEM_BYTES);
    cudaFuncSetAttribute(v_kernel, cudaFuncAttributeMaxDynamicSharedMemorySize,
                         GSMEM_BYTES);
    cudaFuncSetAttribute(scores_kernel, cudaFuncAttributeMaxDynamicSharedMemorySize,
                         GSMEM_BYTES);
    cudaFuncSetAttribute(ax_kernel, cudaFuncAttributeMaxDynamicSharedMemorySize,
                         GSMEM_BYTES);

    prep_x<<<dim3(8, 8, 32), 256>>>(x);
    prep_w<<<dim3(128, 2), 256>>>(Wq, Wk);
    wprime_kernel<<<dim3(4, 4), 512, GSMEM_BYTES>>>();
    vecs_kernel<<<65, 256>>>(Wq, bk, Wk, bq);
    r_kernel<<<2048, 256>>>();
    v_kernel<<<dim3(4, 128), 512, GSMEM_BYTES>>>();
    scores_kernel<<<dim3(4, 4, 32), 512, GSMEM_BYTES>>>();
    rowsum_kernel<<<2048, 256>>>(attn);
    ax_kernel<<<dim3(4, 4, 32), 512, GSMEM_BYTES>>>();
    final_kernel<<<dim3(4, KSPLIT), 256>>>(Wm);
    reduce_kernel<<<64, 256>>>(out, bm);
}

// round 17
// speedup vs baseline: 1.2012x; 1.0139x over previous
#include <cuda_runtime.h>
#include <cuda_fp16.h>
#include <stdint.h>
#include <math.h>

/* GEMM pipeline constants */
#define GBK 64
#define GASTR 72
#define GNITER 8
#define GSTAGES 3

/* final kernel constants */
#define FBK 32
#define FASTR 40
#define KSPLIT 64
#define KCHUNK 4096
#define BN_LD 136

/* Scratch: __device__ globals (allocation-free rule) */
__device__ uint16_t xd16[32 * 512 * 512];
__device__ uint16_t xt16[32 * 512 * 512];
__device__ uint16_t wq16[512 * 512];
__device__ uint16_t wk16[512 * 512];
__device__ uint16_t wpt16[512 * 512];
__device__ uint16_t v16[32 * 512 * 512];
__device__ uint16_t at16[32 * 512 * 512];
__device__ uint16_t ax16[32 * 512 * 512];
__device__ float g_rinv[32 * 512];
__device__ float g_wqbk[512];
__device__ float g_wkbq[512];
__device__ float g_c0[1];
__device__ float g_r1[32 * 512];
__device__ float g_r2[32 * 512];
__device__ float g_part[KSPLIT * 32 * 512];

/* ------------------------------------------------------------------ */
__device__ __forceinline__ uint32_t sptr(const void* p) {
    return (uint32_t)__cvta_generic_to_shared(p);
}

__device__ __forceinline__ void ldsm_x4(uint32_t& r0, uint32_t& r1,
                                        uint32_t& r2, uint32_t& r3,
                                        uint32_t addr) {
    asm volatile("ldmatrix.sync.aligned.m8n8.x4.shared.b16 {%0,%1,%2,%3}, [%4];"
                 : "=r"(r0), "=r"(r1), "=r"(r2), "=r"(r3)
                 : "r"(addr));
}

__device__ __forceinline__ void ldsm_x4_trans(uint32_t& r0, uint32_t& r1,
                                              uint32_t& r2, uint32_t& r3,
                                              uint32_t addr) {
    asm volatile("ldmatrix.sync.aligned.m8n8.x4.trans.shared.b16 {%0,%1,%2,%3}, [%4];"
                 : "=r"(r0), "=r"(r1), "=r"(r2), "=r"(r3)
                 : "r"(addr));
}

__device__ __forceinline__ void mma_f16(float* c, const uint32_t* a,
                                        const uint32_t* b) {
    asm volatile(
        "mma.sync.aligned.m16n8k16.row.col.f32.f16.f16.f32 "
        "{%0,%1,%2,%3}, {%4,%5,%6,%7}, {%8,%9}, {%0,%1,%2,%3};"
        : "+f"(c[0]), "+f"(c[1]), "+f"(c[2]), "+f"(c[3])
        : "r"(a[0]), "r"(a[1]), "r"(a[2]), "r"(a[3]),
          "r"(b[0]), "r"(b[1]));
}

__device__ __forceinline__ void cpa16(uint32_t dst, const void* src) {
    asm volatile("cp.async.cg.shared.global [%0], [%1], 16;"
                 :: "r"(dst), "l"(src) : "memory");
}
__device__ __forceinline__ void cpa_commit() {
    asm volatile("cp.async.commit_group;" ::: "memory");
}
template <int N>
__device__ __forceinline__ void cpa_wait() {
    asm volatile("cp.async.wait_group %0;" :: "n"(N) : "memory");
}

__device__ __forceinline__ uint16_t h1(float v) {
    __half h = __float2half_rn(v);
    return *reinterpret_cast<uint16_t*>(&h);
}

__device__ __forceinline__ void pack8_plain(const float* v, uint4& u) {
    uint16_t h[8];
#pragma unroll
    for (int j = 0; j < 8; j++) {
        h[j] = h1(v[j]);
    }
    u.x = (uint32_t)h[0] | ((uint32_t)h[1] << 16);
    u.y = (uint32_t)h[2] | ((uint32_t)h[3] << 16);
    u.z = (uint32_t)h[4] | ((uint32_t)h[5] << 16);
    u.w = (uint32_t)h[6] | ((uint32_t)h[7] << 16);
}

/* ------------------------------------------------------------------ */
/* Compute: one GBK=64 slab, 128x128 CTA tile, 16 warps, 32x32 tiles.  */
/* ------------------------------------------------------------------ */
__device__ __forceinline__ void compute128_h(uint32_t sA, uint32_t sB,
                                             int wm, int wn, int lane,
                                             float acc[2][4][4]) {
    const int lr = (lane & 7) + ((lane >> 3) & 1) * 8;
    const int lc = (lane >> 4) * 8;

#pragma unroll
    for (int h = 0; h < 4; h++) {
        uint32_t b[4][2];
#pragma unroll
        for (int p = 0; p < 2; p++) {
            uint32_t off = (uint32_t)(((wn * 32 + p * 16 + lr) * GASTR + h * 16 + lc) * 2);
            uint32_t r0, r1, r2, r3;
            ldsm_x4(r0, r1, r2, r3, sB + off);
            b[2 * p][0] = r0;
            b[2 * p][1] = r2;
            b[2 * p + 1][0] = r1;
            b[2 * p + 1][1] = r3;
        }
        uint32_t a[2][4];
#pragma unroll
        for (int mt = 0; mt < 2; mt++) {
            uint32_t off = (uint32_t)(((wm * 32 + mt * 16 + lr) * GASTR + h * 16 + lc) * 2);
            ldsm_x4(a[mt][0], a[mt][1], a[mt][2], a[mt][3], sA + off);
        }
#pragma unroll
        for (int mt = 0; mt < 2; mt++) {
#pragma unroll
            for (int nt = 0; nt < 4; nt++) {
                mma_f16(acc[mt][nt], a[mt], b[nt]);
            }
        }
    }
}

/* ------------------------------------------------------------------ */
/* Prep 1: x -> xd16 + xt16.                                           */
/* ------------------------------------------------------------------ */
__global__ __launch_bounds__(256) void prep_x(const float* __restrict__ x) {
    __shared__ float ts[64][65];
    const int tid = threadIdx.x;
    const int m0 = blockIdx.y * 64;
    const int h0 = blockIdx.x * 64;
    const size_t off = (size_t)blockIdx.z * 262144;
    const float* src = x + off + (size_t)m0 * 512 + h0;

#pragma unroll
    for (int i = 0; i < 4; i++) {
        int lin = i * 256 + tid;
        int r = lin >> 4;
        int c4 = (lin & 15) * 4;
        float4 v = *(const float4*)(src + (size_t)r * 512 + c4);
        ts[r][c4 + 0] = v.x;
        ts[r][c4 + 1] = v.y;
        ts[r][c4 + 2] = v.z;
        ts[r][c4 + 3] = v.w;
    }
    __syncthreads();

#pragma unroll
    for (int i = 0; i < 2; i++) {
        int lin = i * 256 + tid;
        int r = lin >> 3;
        int c8 = (lin & 7) * 8;
        float v[8];
#pragma unroll
        for (int j = 0; j < 8; j++) {
            v[j] = ts[r][c8 + j];
        }
        uint4 u;
        pack8_plain(v, u);
        *(uint4*)(xd16 + off + (size_t)(m0 + r) * 512 + h0 + c8) = u;
    }
#pragma unroll
    for (int i = 0; i < 2; i++) {
        int lin = i * 256 + tid;
        int hr = lin >> 3;
        int m8 = (lin & 7) * 8;
        float v[8];
#pragma unroll
        for (int j = 0; j < 8; j++) {
            v[j] = ts[m8 + j][hr];
        }
        uint4 u;
        pack8_plain(v, u);
        *(uint4*)(xt16 + off + (size_t)(h0 + hr) * 512 + m0 + m8) = u;
    }
}

/* ------------------------------------------------------------------ */
/* Prep 2: Wq/Wk -> direct fp16. grid (128, 2) x 256.                  */
/* ------------------------------------------------------------------ */
__global__ __launch_bounds__(256) void prep_w(const float* __restrict__ Wq,
                                              const float* __restrict__ Wk) {
    const float* src = blockIdx.y ? Wk : Wq;
    uint16_t* dst = blockIdx.y ? wk16 : wq16;
    int lin = blockIdx.x * 256 + threadIdx.x;
    size_t e = (size_t)lin * 8;
    float v[8];
    float4 a = *(const float4*)(src + e);
    float4 b = *(const float4*)(src + e + 4);
    v[0] = a.x; v[1] = a.y; v[2] = a.z; v[3] = a.w;
    v[4] = b.x; v[5] = b.y; v[6] = b.z; v[7] = b.w;
    uint4 u;
    pack8_plain(v, u);
    *(uint4*)(dst + e) = u;
}

/* ------------------------------------------------------------------ */
/* GEMM body: 3-stage cp.async pipeline, GBK=64, 512 threads.          */
/* ------------------------------------------------------------------ */
#define PTILE (128 * GASTR)
#define STAGE_BYTES (2 * PTILE * 2)
#define GSMEM_BYTES (GSTAGES * STAGE_BYTES)

__device__ __forceinline__ void gemm128_body(
    const uint16_t* __restrict__ A, const uint16_t* __restrict__ B,
    uint32_t s0addr, int tid, int wm, int wn, int lane, float acc[2][4][4]) {
    const int trow = tid >> 3;
    const int tcol = (tid & 7) * 8;
    const uint16_t* pa = A + (size_t)trow * 512 + tcol;
    const uint16_t* pb = B + (size_t)trow * 512 + tcol;
    const uint32_t soff = (uint32_t)(trow * GASTR + tcol) * 2;

#pragma unroll
    for (int s = 0; s < GSTAGES - 1; s++) {
        uint32_t sb = s0addr + s * STAGE_BYTES + soff;
#pragma unroll
        for (int i = 0; i < 2; i++) {
            cpa16(sb + i * (64 * GASTR * 2), pa + i * (64 * 512));
            cpa16(sb + PTILE * 2 + i * (64 * GASTR * 2), pb + i * (64 * 512));
        }
        cpa_commit();
        pa += GBK;
        pb += GBK;
    }

    int cur = 0;
    int nxt = 2;
    for (int c = 0; c < GNITER; c++) {
        cpa_wait<1>();
        __syncthreads();
        if (c + GSTAGES - 1 < GNITER) {
            uint32_t sb = s0addr + nxt * STAGE_BYTES + soff;
#pragma unroll
            for (int i = 0; i < 2; i++) {
                cpa16(sb + i * (64 * GASTR * 2), pa + i * (64 * 512));
                cpa16(sb + PTILE * 2 + i * (64 * GASTR * 2), pb + i * (64 * 512));
            }
            pa += GBK;
            pb += GBK;
        }
        cpa_commit();
        uint32_t sb = s0addr + cur * STAGE_BYTES;
        compute128_h(sb, sb + PTILE * 2, wm, wn, lane, acc);
        cur = (cur == 2) ? 0 : cur + 1;
        nxt = (nxt == 2) ? 0 : nxt + 1;
    }
}

/* ------------------------------------------------------------------ */
/* Kernel: W'^T = (Wq @ Wk^T)^T -> wpt16, PLUS bias vectors.           */
/* grid (4,5): y<4 = GEMM tiles; y==4 = vecs (g_wqbk/g_wkbq/c0).       */
/* ------------------------------------------------------------------ */
__global__ __launch_bounds__(512, 2) void wprime_kernel(
    const float* __restrict__ Wq, const float* __restrict__ bk,
    const float* __restrict__ Wk, const float* __restrict__ bq) {
    extern __shared__ uint16_t dynsm[];

    const int tid = threadIdx.x;
    const int lane = tid & 31;
    const int wid = tid >> 5;

    if (blockIdx.y == 4) {
        /* vecs: 4 blocks x 16 warps x 8 rows = 512 h rows */
#pragma unroll
        for (int i = 0; i < 8; i++) {
            const int h = blockIdx.x * 128 + wid * 8 + i;
            float s1 = 0.f;
            float s2 = 0.f;
#pragma unroll
            for (int j = 0; j < 16; j++) {
                int d = lane + j * 32;
                s1 += Wq[(size_t)h * 512 + d] * bk[d];
                s2 += Wk[(size_t)h * 512 + d] * bq[d];
            }
#pragma unroll
            for (int o = 16; o > 0; o >>= 1) {
                s1 += __shfl_xor_sync(0xffffffffu, s1, o);
                s2 += __shfl_xor_sync(0xffffffffu, s2, o);
            }
            if (lane == 0) {
                g_wqbk[h] = s1;
                g_wkbq[h] = s2;
            }
        }
        if (blockIdx.x == 0 && wid == 0) {
            float s = 0.f;
#pragma unroll
            for (int j = 0; j < 16; j++) {
                int d = lane + j * 32;
                s += bq[d] * bk[d];
            }
#pragma unroll
            for (int o = 16; o > 0; o >>= 1) {
                s += __shfl_xor_sync(0xffffffffu, s, o);
            }
            if (lane == 0) {
                g_c0[0] = s;
            }
        }
        return;
    }

    const int wm = wid & 3;
    const int wn = wid >> 2;
    const int row0 = blockIdx.y * 128;
    const int col0 = blockIdx.x * 128;

    float acc[2][4][4] = {};
    gemm128_body(wq16 + (size_t)row0 * 512, wk16 + (size_t)col0 * 512,
                 sptr(dynsm), tid, wm, wn, lane, acc);

    const int g = lane >> 2;
    const int tg2 = (lane & 3) * 2;
#pragma unroll
    for (int mt = 0; mt < 2; mt++) {
        int r = row0 + wm * 32 + mt * 16 + g;
#pragma unroll
        for (int nt = 0; nt < 4; nt++) {
            int c = col0 + wn * 32 + nt * 8 + tg2;
            wpt16[(size_t)c * 512 + r] = h1(acc[mt][nt][0]);
            wpt16[(size_t)(c + 1) * 512 + r] = h1(acc[mt][nt][1]);
            wpt16[(size_t)c * 512 + r + 8] = h1(acc[mt][nt][2]);
            wpt16[(size_t)(c + 1) * 512 + r + 8] = h1(acc[mt][nt][3]);
        }
    }
}

/* ------------------------------------------------------------------ */
/* Kernel: v = x @ W'. grid (4, 128), 512 thr. Blocks with x==0 also   */
/* compute r1/r2 for their 128 rows (warp-per-8-rows dot products).    */
/* ------------------------------------------------------------------ */
__global__ __launch_bounds__(512, 2) void v_kernel() {
    extern __shared__ uint16_t dynsm[];

    const int tid = threadIdx.x;
    const int lane = tid & 31;
    const int wid = tid >> 5;
    const int wm = wid & 3;
    const int wn = wid >> 2;
    const int row0 = blockIdx.y * 128;
    const int col0 = blockIdx.x * 128;

    const uint16_t* A = xd16 + (size_t)row0 * 512;
    const uint16_t* B = wpt16 + (size_t)col0 * 512;

    float acc[2][4][4] = {};
    gemm128_body(A, B, sptr(dynsm), tid, wm, wn, lane, acc);

    const int g = lane >> 2;
    const int tg2 = (lane & 3) * 2;
#pragma unroll
    for (int mt = 0; mt < 2; mt++) {
        int r = row0 + wm * 32 + mt * 16 + g;
#pragma unroll
        for (int nt = 0; nt < 4; nt++) {
            int c = col0 + wn * 32 + nt * 8 + tg2;
            __half2 p0 = __floats2half2_rn(acc[mt][nt][0], acc[mt][nt][1]);
            __half2 p1 = __floats2half2_rn(acc[mt][nt][2], acc[mt][nt][3]);
            *(uint32_t*)(v16 + (size_t)r * 512 + c) = *reinterpret_cast<uint32_t*>(&p0);
            *(uint32_t*)(v16 + (size_t)(r + 8) * 512 + c) = *reinterpret_cast<uint32_t*>(&p1);
        }
    }

    if (blockIdx.x == 0) {
#pragma unroll
        for (int i = 0; i < 8; i++) {
            const size_t row = (size_t)row0 + wid * 8 + i;
            const uint16_t* p = xd16 + row * 512;
            float s1 = 0.f;
            float s2 = 0.f;
#pragma unroll
            for (int j = 0; j < 2; j++) {
                int cb = j * 256 + lane * 8;
                uint4 u = *(const uint4*)(p + cb);
                float2 f0 = __half22float2(*reinterpret_cast<__half2*>(&u.x));
                float2 f1 = __half22float2(*reinterpret_cast<__half2*>(&u.y));
                float2 f2 = __half22float2(*reinterpret_cast<__half2*>(&u.z));
                float2 f3 = __half22float2(*reinterpret_cast<__half2*>(&u.w));
                s1 += f0.x * g_wqbk[cb] + f0.y * g_wqbk[cb + 1] +
                      f1.x * g_wqbk[cb + 2] + f1.y * g_wqbk[cb + 3] +
                      f2.x * g_wqbk[cb + 4] + f2.y * g_wqbk[cb + 5] +
                      f3.x * g_wqbk[cb + 6] + f3.y * g_wqbk[cb + 7];
                s2 += f0.x * g_wkbq[cb] + f0.y * g_wkbq[cb + 1] +
                      f1.x * g_wkbq[cb + 2] + f1.y * g_wkbq[cb + 3] +
                      f2.x * g_wkbq[cb + 4] + f2.y * g_wkbq[cb + 5] +
                      f3.x * g_wkbq[cb + 6] + f3.y * g_wkbq[cb + 7];
            }
#pragma unroll
            for (int o = 16; o > 0; o >>= 1) {
                s1 += __shfl_xor_sync(0xffffffffu, s1, o);
                s2 += __shfl_xor_sync(0xffffffffu, s2, o);
            }
            if (lane == 0) {
                g_r1[row] = s1;
                g_r2[row] = s2;
            }
        }
    }
}

/* ------------------------------------------------------------------ */
/* Kernel: scores -> at16 = exp(sigmoid((v x^T + r1 + r2 + c0)/sq)).   */
/* ------------------------------------------------------------------ */
__device__ __forceinline__ float esig(float x, float scale) {
    return __expf(__fdividef(1.f, 1.f + __expf(-x * scale)));
}

__global__ __launch_bounds__(512, 2) void scores_kernel() {
    extern __shared__ uint16_t dynsm[];

    const int tid = threadIdx.x;
    const int lane = tid & 31;
    const int wid = tid >> 5;
    const int wm = wid & 3;
    const int wn = wid >> 2;
    const int b = blockIdx.z;
    const int row0 = blockIdx.y * 128;
    const int col0 = blockIdx.x * 128;

    const uint16_t* A = v16 + ((size_t)b * 512 + row0) * 512;
    const uint16_t* B = xd16 + ((size_t)b * 512 + col0) * 512;

    float acc[2][4][4] = {};
    gemm128_body(A, B, sptr(dynsm), tid, wm, wn, lane, acc);

    const float scale = 0.04419417382415922f;
    const float c0v = g_c0[0];
    uint16_t* E = at16 + (size_t)b * 262144;
    const int g = lane >> 2;
    const int tg2 = (lane & 3) * 2;
#pragma unroll
    for (int mt = 0; mt < 2; mt++) {
        int r = row0 + wm * 32 + mt * 16 + g;
        float r1a = g_r1[(size_t)b * 512 + r] + c0v;
        float r1b = g_r1[(size_t)b * 512 + r + 8] + c0v;
#pragma unroll
        for (int nt = 0; nt < 4; nt++) {
            int c = col0 + wn * 32 + nt * 8 + tg2;
            float2 r2v = *(const float2*)(g_r2 + (size_t)b * 512 + c);
            __half2 p0 = __floats2half2_rn(
                esig(acc[mt][nt][0] + r1a + r2v.x, scale),
                esig(acc[mt][nt][1] + r1a + r2v.y, scale));
            __half2 p1 = __floats2half2_rn(
                esig(acc[mt][nt][2] + r1b + r2v.x, scale),
                esig(acc[mt][nt][3] + r1b + r2v.y, scale));
            *(uint32_t*)(E + (size_t)r * 512 + c) = *reinterpret_cast<uint32_t*>(&p0);
            *(uint32_t*)(E + (size_t)(r + 8) * 512 + c) = *reinterpret_cast<uint32_t*>(&p1);
        }
    }
}

/* ------------------------------------------------------------------ */
/* Kernel: warp-per-row rowsum (uint4 loads). grid 2048 x 256.         */
/* ------------------------------------------------------------------ */
__global__ __launch_bounds__(256) void rowsum_kernel(float* __restrict__ attn) {
    const int w = threadIdx.x >> 5;
    const int lane = threadIdx.x & 31;
    const size_t row = (size_t)blockIdx.x * 8 + w;
    const size_t base = row * 512;

    uint4 u[2];
#pragma unroll
    for (int i = 0; i < 2; i++) {
        u[i] = *(const uint4*)(at16 + base + i * 256 + lane * 8);
    }
    float e[16];
    float s = 0.f;
#pragma unroll
    for (int i = 0; i < 2; i++) {
        float2 f0 = __half22float2(*reinterpret_cast<__half2*>(&u[i].x));
        float2 f1 = __half22float2(*reinterpret_cast<__half2*>(&u[i].y));
        float2 f2 = __half22float2(*reinterpret_cast<__half2*>(&u[i].z));
        float2 f3 = __half22float2(*reinterpret_cast<__half2*>(&u[i].w));
        e[i * 8 + 0] = f0.x;
        e[i * 8 + 1] = f0.y;
        e[i * 8 + 2] = f1.x;
        e[i * 8 + 3] = f1.y;
        e[i * 8 + 4] = f2.x;
        e[i * 8 + 5] = f2.y;
        e[i * 8 + 6] = f3.x;
        e[i * 8 + 7] = f3.y;
        s += f0.x + f0.y + f1.x + f1.y + f2.x + f2.y + f3.x + f3.y;
    }
#pragma unroll
    for (int o = 16; o > 0; o >>= 1) {
        s += __shfl_xor_sync(0xffffffffu, s, o);
    }
    const float inv = 1.f / s;
    if (lane == 0) {
        g_rinv[row] = inv;
    }
#pragma unroll
    for (int i = 0; i < 2; i++) {
#pragma unroll
        for (int j = 0; j < 2; j++) {
            float4 o;
            o.x = e[i * 8 + j * 4 + 0] * inv;
            o.y = e[i * 8 + j * 4 + 1] * inv;
            o.z = e[i * 8 + j * 4 + 2] * inv;
            o.w = e[i * 8 + j * 4 + 3] * inv;
            *(float4*)(attn + base + i * 256 + lane * 8 + j * 4) = o;
        }
    }
}

/* ------------------------------------------------------------------ */
/* Kernel: ax = softmax @ x. grid (4,4,32), 512 thr.                   */
/* ------------------------------------------------------------------ */
__global__ __launch_bounds__(512, 2) void ax_kernel() {
    extern __shared__ uint16_t dynsm[];

    const int tid = threadIdx.x;
    const int lane = tid & 31;
    const int wid = tid >> 5;
    const int wm = wid & 3;
    const int wn = wid >> 2;
    const int b = blockIdx.z;
    const int row0 = blockIdx.y * 128;
    const int col0 = blockIdx.x * 128;

    const uint16_t* A = at16 + ((size_t)b * 512 + row0) * 512;
    const uint16_t* B = xt16 + ((size_t)b * 512 + col0) * 512;

    float acc[2][4][4] = {};
    gemm128_body(A, B, sptr(dynsm), tid, wm, wn, lane, acc);

    const size_t rowg = (size_t)b * 512;
    const int g = lane >> 2;
    const int tg2 = (lane & 3) * 2;
#pragma unroll
    for (int mt = 0; mt < 2; mt++) {
        int r = row0 + wm * 32 + mt * 16 + g;
        float i0 = g_rinv[rowg + r];
        float i1 = g_rinv[rowg + r + 8];
#pragma unroll
        for (int nt = 0; nt < 4; nt++) {
            int c = col0 + wn * 32 + nt * 8 + tg2;
            __half2 p0 = __floats2half2_rn(acc[mt][nt][0] * i0, acc[mt][nt][1] * i0);
            __half2 p1 = __floats2half2_rn(acc[mt][nt][2] * i1, acc[mt][nt][3] * i1);
            *(uint32_t*)(ax16 + (rowg + r) * 512 + c) = *reinterpret_cast<uint32_t*>(&p0);
            *(uint32_t*)(ax16 + (rowg + r + 8) * 512 + c) = *reinterpret_cast<uint32_t*>(&p1);
        }
    }
}

/* ------------------------------------------------------------------ */
/* Kernel: split-K partials of out = ax.reshape(32,262144) @ Wm.       */
/* ------------------------------------------------------------------ */
#define FAEL (32 * FASTR)
#define FBEL (32 * BN_LD)
#define FSTAGE (FAEL + FBEL)

__global__ __launch_bounds__(256, 2) void final_kernel(const float* __restrict__ Wm) {
    __shared__ alignas(16) uint16_t dsm[2 * FSTAGE];

    const int tid = threadIdx.x;
    const int lane = tid & 31;
    const int wid = tid >> 5;
    const int col0 = blockIdx.x * 128;
    const size_t kbase = (size_t)blockIdx.y * KCHUNK;

    float acc[2][2][4] = {};
    uint2 va;
    float4 vb[4];
    const int am = tid >> 3;
    const int ak = (tid & 7) * 4;
    const int bk_r = tid >> 5;
    const int bn4 = (tid & 31) * 4;

    va = *(const uint2*)(ax16 + (size_t)am * 262144 + kbase + ak);
#pragma unroll
    for (int i = 0; i < 4; i++) {
        vb[i] = *(const float4*)(Wm + (kbase + bk_r + i * 8) * 512 + col0 + bn4);
    }

    auto store_stage = [&](uint16_t* stg) {
        *(uint2*)(stg + am * FASTR + ak) = va;
        uint16_t* bs = stg + FAEL;
#pragma unroll
        for (int i = 0; i < 4; i++) {
            __half2 p0 = __floats2half2_rn(vb[i].x, vb[i].y);
            __half2 p1 = __floats2half2_rn(vb[i].z, vb[i].w);
            uint2 u;
            u.x = *reinterpret_cast<uint32_t*>(&p0);
            u.y = *reinterpret_cast<uint32_t*>(&p1);
            *(uint2*)(bs + (bk_r + i * 8) * BN_LD + bn4) = u;
        }
    };

    store_stage(dsm);
    va = *(const uint2*)(ax16 + (size_t)am * 262144 + kbase + FBK + ak);
#pragma unroll
    for (int i = 0; i < 4; i++) {
        vb[i] = *(const float4*)(Wm + (kbase + FBK + bk_r + i * 8) * 512 + col0 + bn4);
    }
    __syncthreads();

    const int lr = (lane & 7) + ((lane >> 3) & 1) * 8;
    const int lc = (lane >> 4) * 8;
    const int trow = (lane >> 4) * 8 + (lane & 7);
    const int tcol = ((lane >> 3) & 1) * 8;

    for (int k0 = 0; k0 < KCHUNK; k0 += FBK) {
        int cur = (k0 >> 5) & 1;
        if (k0 + FBK < KCHUNK) {
            store_stage(dsm + (cur ^ 1) * FSTAGE);
        }
        if (k0 + 2 * FBK < KCHUNK) {
            va = *(const uint2*)(ax16 + (size_t)am * 262144 + kbase + k0 + 2 * FBK + ak);
#pragma unroll
            for (int i = 0; i < 4; i++) {
                vb[i] = *(const float4*)(Wm + (kbase + k0 + 2 * FBK + bk_r + i * 8) * 512 +
                                         col0 + bn4);
            }
        }
        uint32_t base = sptr(dsm) + cur * FSTAGE * 2;
        uint32_t sA = base;
        uint32_t sB = base + FAEL * 2;
#pragma unroll
        for (int ks = 0; ks < FBK; ks += 16) {
            uint32_t bf[2][2];
            uint32_t offb = (uint32_t)(((ks + trow) * BN_LD + wid * 16 + tcol) * 2);
            uint32_t r0, r1, r2, r3;
            ldsm_x4_trans(r0, r1, r2, r3, sB + offb);
            bf[0][0] = r0;
            bf[1][0] = r1;
            bf[0][1] = r2;
            bf[1][1] = r3;
            uint32_t a[2][4];
#pragma unroll
            for (int mt = 0; mt < 2; mt++) {
                uint32_t offa = (uint32_t)(((mt * 16 + lr) * FASTR + ks + lc) * 2);
                ldsm_x4(a[mt][0], a[mt][1], a[mt][2], a[mt][3], sA + offa);
            }
#pragma unroll
            for (int mt = 0; mt < 2; mt++) {
#pragma unroll
                for (int nt = 0; nt < 2; nt++) {
                    mma_f16(acc[mt][nt], a[mt], bf[nt]);
                }
            }
        }
        __syncthreads();
    }

    const int g = lane >> 2;
    const int tg2 = (lane & 3) * 2;
    float* P = g_part + (size_t)blockIdx.y * 16384;
#pragma unroll
    for (int mt = 0; mt < 2; mt++) {
        int r = mt * 16 + g;
#pragma unroll
        for (int nt = 0; nt < 2; nt++) {
            int c = col0 + wid * 16 + nt * 8 + tg2;
            float2 o0;
            float2 o1;
            o0.x = acc[mt][nt][0];
            o0.y = acc[mt][nt][1];
            o1.x = acc[mt][nt][2];
            o1.y = acc[mt][nt][3];
            *(float2*)(P + (size_t)r * 512 + c) = o0;
            *(float2*)(P + (size_t)(r + 8) * 512 + c) = o1;
        }
    }
}

/* ------------------------------------------------------------------ */
/* Kernel: deterministic split-K reduce + bias. grid 64 x 256.         */
/* ------------------------------------------------------------------ */
__global__ __launch_bounds__(256) void reduce_kernel(float* __restrict__ out,
                                                     const float* __restrict__ bm) {
    const int idx = blockIdx.x * 256 + threadIdx.x;
    const int n = idx & 511;
    float sum = bm[n];
#pragma unroll 8
    for (int s = 0; s < KSPLIT; s++) {
        sum += g_part[(size_t)s * 16384 + idx];
    }
    out[idx] = sum;
}

/* ------------------------------------------------------------------ */
extern "C" void kernel_launch(void* const* d_in, const int* in_sizes, int n_in,
                              void* d_out, int out_size) {
    const float* x = (const float*)d_in[0];
    const float* Wq = (const float*)d_in[1];
    const float* bq = (const float*)d_in[2];
    const float* Wk = (const float*)d_in[3];
    const float* bk = (const float*)d_in[4];
    const float* Wm = (const float*)d_in[5];
    const float* bm = (const float*)d_in[6];

    float* out = (float*)d_out;
    float* attn = out + 32 * 512;

    cudaFuncSetAttribute(wprime_kernel, cudaFuncAttributeMaxDynamicSharedMemorySize,
                         GSMEM_BYTES);
    cudaFuncSetAttribute(v_kernel, cudaFuncAttributeMaxDynamicSharedMemorySize,
                         GSMEM_BYTES);
    cudaFuncSetAttribute(scores_kernel, cudaFuncAttributeMaxDynamicSharedMemorySize,
                         GSMEM_BYTES);
    cudaFuncSetAttribute(ax_kernel, cudaFuncAttributeMaxDynamicSharedMemorySize,
                         GSMEM_BYTES);

    prep_x<<<dim3(8, 8, 32), 256>>>(x);
    prep_w<<<dim3(128, 2), 256>>>(Wq, Wk);
    wprime_kernel<<<dim3(4, 5), 512, GSMEM_BYTES>>>(Wq, bk, Wk, bq);
    v_kernel<<<dim3(4, 128), 512, GSMEM_BYTES>>>();
    scores_kernel<<<dim3(4, 4, 32), 512, GSMEM_BYTES>>>();
    rowsum_kernel<<<2048, 256>>>(attn);
    ax_kernel<<<dim3(4, 4, 32), 512, GSMEM_BYTES>>>();
    final_kernel<<<dim3(4, KSPLIT), 256>>>(Wm);
    reduce_kernel<<<64, 256>>>(out, bm);
}